// round 1
// baseline (speedup 1.0000x reference)
#include <cuda_runtime.h>

#define NN 10000
#define EE 50000
#define NC 25
#define CC 64
#define C2 128
#define NHEADS 8
#define ACH 16
#define VCH 8
#define FFD 128
#define GG 36

__constant__ int c_lof[NC] = {0,1,1,1,2,2,2,2,2,3,3,3,3,3,3,3,4,4,4,4,4,4,4,4,4};

// Scratch (device globals: allocation-free rule)
__device__ float    g_h[(size_t)NN*NC*CC];        // rmsnorm1 output
__device__ float    g_r[(size_t)EE*5*C2];         // radial MLP output
__device__ float    g_msg[(size_t)EE*NC*CC];      // per-edge messages
__device__ float    g_alpha[EE*NHEADS];
__device__ float    g_ez[EE*NHEADS];
__device__ unsigned g_amax[NN*NHEADS];
__device__ float    g_asum[NN*NHEADS];
__device__ float    g_agg[(size_t)NN*NC*CC];

__device__ __forceinline__ float silu(float x){ return x/(1.f+__expf(-x)); }

__device__ __forceinline__ unsigned enc_f(float x){
  unsigned b = __float_as_uint(x);
  return (b & 0x80000000u) ? ~b : (b | 0x80000000u);
}
__device__ __forceinline__ float dec_f(unsigned u){
  unsigned b = (u & 0x80000000u) ? (u & 0x7FFFFFFFu) : ~u;
  return __uint_as_float(b);
}

// ---------------- rmsnorm over coef axis ----------------
__global__ void k_rms1(const float* __restrict__ x, const float* __restrict__ gamma){
  int n = blockIdx.x*4 + threadIdx.y;
  if(n >= NN) return;
  int c = threadIdx.x;
  const float* xp = x + (size_t)n*1600 + c;
  float s = 0.f;
  #pragma unroll
  for(int i=0;i<NC;i++){ float v = xp[i*64]; s += v*v; }
  float gm = rsqrtf(s*(1.f/25.f) + 1e-6f) * gamma[c];
  float* hp = g_h + (size_t)n*1600 + c;
  #pragma unroll
  for(int i=0;i<NC;i++) hp[i*64] = xp[i*64]*gm;
}

// ---------------- radial MLP (weights SMEM-resident) ----------------
__global__ void k_rad(const float* __restrict__ ed, const int* __restrict__ ei,
                      const int* __restrict__ zn,
                      const float* __restrict__ st, const float* __restrict__ tt,
                      const float* __restrict__ w1, const float* __restrict__ b1,
                      const float* __restrict__ w2, const float* __restrict__ b2,
                      const float* __restrict__ w3, const float* __restrict__ b3)
{
  extern __shared__ float sm[];
  float* sw1 = sm;          // 96*64
  float* sw2 = sw1 + 6144;  // 64*64
  float* sw3 = sw2 + 4096;  // 64*640
  float* sb1 = sw3 + 40960; // 64
  float* sb2 = sb1 + 64;    // 64
  float* sb3 = sb2 + 64;    // 640
  float* ef  = sb3 + 640;   // 4*96
  float* h1  = ef + 384;    // 4*64
  float* h2  = h1 + 256;    // 4*64
  int tid = threadIdx.x;
  for(int i=tid;i<6144;i+=256)  sw1[i]=w1[i];
  for(int i=tid;i<4096;i+=256)  sw2[i]=w2[i];
  for(int i=tid;i<40960;i+=256) sw3[i]=w3[i];
  if(tid<64){ sb1[tid]=b1[tid]; sb2[tid]=b2[tid]; }
  for(int i=tid;i<640;i+=256)   sb3[i]=b3[i];
  __syncthreads();

  int grp = tid>>6, t = tid&63;
  int iters = (EE + (int)gridDim.x*4 - 1)/((int)gridDim.x*4);
  for(int it=0; it<iters; it++){
    int e = (it*(int)gridDim.x + (int)blockIdx.x)*4 + grp;
    bool valid = (e < EE);
    if(valid && t<32){
      int src = ei[e], dst = ei[EE+e];
      ef[grp*96+t]      = ed[(size_t)e*32+t];
      ef[grp*96+32+t]   = st[zn[src]*32+t];
      ef[grp*96+64+t]   = tt[zn[dst]*32+t];
    }
    __syncthreads();
    if(valid){
      float acc = sb1[t];
      #pragma unroll 8
      for(int k=0;k<96;k++) acc += ef[grp*96+k]*sw1[k*64+t];
      h1[grp*64+t] = silu(acc);
    }
    __syncthreads();
    if(valid){
      float acc = sb2[t];
      #pragma unroll 8
      for(int k=0;k<64;k++) acc += h1[grp*64+k]*sw2[k*64+t];
      h2[grp*64+t] = silu(acc);
    }
    __syncthreads();
    if(valid){
      float* rp = g_r + (size_t)e*640;
      for(int o=t;o<640;o+=64){
        float acc = sb3[o];
        #pragma unroll 8
        for(int k=0;k<64;k++) acc += h2[grp*64+k]*sw3[k*640+o];
        rp[o] = acc;
      }
    }
    __syncthreads();
  }
}

// ---------------- main per-edge kernel ----------------
__global__ void k_edge(const float* __restrict__ wigner, const int* __restrict__ ei,
                       const float* __restrict__ W1, const float* __restrict__ W0,
                       const float* __restrict__ adot, const float* __restrict__ tg,
                       const float* __restrict__ fg)
{
  extern __shared__ float sm[];
  float* sW1   = sm;            // 128*64
  float* sW0   = sW1 + 8192;    // 128*192
  float* sTG   = sW0 + 24576;   // 36*25
  float* sFG   = sTG + 900;     // 25*36
  float* sAD   = sFG + 900;     // 8*16
  float* wig   = sAD + 128;     // 25*26 (padded)
  float* cat   = wig + 650;     // 25*128
  float* xe    = cat + 3200;    // 25*128
  float* rr    = xe + 3200;     // 640
  float* extra = rr + 640;      // 192
  float* smsg  = extra + 192;   // 25*64
  float* sgrid = smsg + 1600;   // 36*64
  int tid = threadIdx.x;
  for(int i=tid;i<8192;i+=256)  sW1[i]=W1[i];
  for(int i=tid;i<24576;i+=256) sW0[i]=W0[i];
  for(int i=tid;i<900;i+=256){ sTG[i]=tg[i]; sFG[i]=fg[i]; }
  if(tid<128) sAD[tid]=adot[tid];
  __syncthreads();

  for(int e=blockIdx.x; e<EE; e+=gridDim.x){
    int src = ei[e], dst = ei[EE+e];
    const float* wp = wigner + (size_t)e*625;
    for(int i=tid;i<625;i+=256) wig[(i/25)*26 + (i%25)] = wp[i];
    const float* hs = g_h + (size_t)src*1600;
    const float* hd = g_h + (size_t)dst*1600;
    for(int i=tid;i<3200;i+=256){
      int j=i>>7, c=i&127;
      cat[i] = (c<64) ? hs[j*64+c] : hd[j*64+c-64];
    }
    const float* rp = g_r + (size_t)e*640;
    for(int i=tid;i<640;i+=256) rr[i]=rp[i];
    __syncthreads();

    // xe = (wig @ cat) * r[EXPAND]
    for(int idx=tid; idx<3200; idx+=256){
      int i=idx>>7, c=idx&127;
      const float* wr = &wig[i*26];
      float acc = 0.f;
      #pragma unroll
      for(int j=0;j<NC;j++) acc += wr[j]*cat[j*128+c];
      xe[idx] = acc * rr[c_lof[i]*128+c];
    }
    __syncthreads();

    // extra = xe[0,:] @ W0_extra (192 outputs)
    if(tid<192){
      float acc = 0.f;
      #pragma unroll 8
      for(int c=0;c<128;c++) acc += xe[c]*sW0[c*192+tid];
      extra[tid] = acc;
    }
    __syncthreads();

    // alpha + segment max
    if(tid<8){
      float acc = 0.f;
      #pragma unroll
      for(int a=0;a<ACH;a++){ float v = extra[tid*16+a]; acc += silu(v)*sAD[tid*16+a]; }
      g_alpha[e*8+tid] = acc;
      atomicMax(&g_amax[dst*8+tid], enc_f(acc));
    }
    // msg = xe @ W1
    for(int idx=tid; idx<1600; idx+=256){
      int i=idx>>6, h=idx&63;
      float acc = 0.f;
      #pragma unroll 8
      for(int c=0;c<128;c++) acc += xe[i*128+c]*sW1[c*64+h];
      smsg[idx] = acc;
    }
    __syncthreads();
    // grid = silu(to_grid @ msg)
    for(int idx=tid; idx<2304; idx+=256){
      int g=idx>>6, h=idx&63;
      float acc = 0.f;
      #pragma unroll
      for(int i=0;i<NC;i++) acc += sTG[g*25+i]*smsg[i*64+h];
      sgrid[idx] = silu(acc);
    }
    __syncthreads();
    // xg = from_grid @ grid, row 0 := silu(gate)
    float* op = g_msg + (size_t)e*1600;
    for(int idx=tid; idx<1600; idx+=256){
      int i=idx>>6, h=idx&63;
      float v;
      if(i==0) v = silu(extra[128+h]);
      else {
        float acc = 0.f;
        #pragma unroll
        for(int g=0;g<GG;g++) acc += sFG[i*36+g]*sgrid[g*64+h];
        v = acc;
      }
      op[idx] = v;
    }
    __syncthreads();
  }
}

// ---------------- softmax pass 2 ----------------
__global__ void k_att(const int* __restrict__ ei){
  int idx = blockIdx.x*blockDim.x + threadIdx.x;
  if(idx >= EE*NHEADS) return;
  int e = idx>>3, h = idx&7;
  int dst = ei[EE+e];
  float am = dec_f(g_amax[dst*8+h]);
  float ez = __expf(g_alpha[idx]-am);
  g_ez[idx] = ez;
  atomicAdd(&g_asum[dst*8+h], ez);
}

// ---------------- weight + wigner^T + scatter ----------------
__global__ void k_scatter(const float* __restrict__ wigner, const int* __restrict__ ei){
  __shared__ float wig[650];
  __shared__ float msgw[1600];
  __shared__ float wgt[8];
  int e = blockIdx.x;
  int tid = threadIdx.x;
  int dst = ei[EE+e];
  if(tid<8){
    float z = g_ez[e*8+tid];
    float s = g_asum[dst*8+tid];
    wgt[tid] = z/(s+1e-8f);
  }
  const float* wp = wigner + (size_t)e*625;
  for(int i=tid;i<625;i+=128) wig[(i/25)*26+(i%25)] = wp[i];
  __syncthreads();
  const float* mp = g_msg + (size_t)e*1600;
  for(int i=tid;i<1600;i+=128){
    int c = i&63;
    msgw[i] = mp[i]*wgt[c>>3];
  }
  __syncthreads();
  float* ap = g_agg + (size_t)dst*1600;
  for(int idx=tid; idx<1600; idx+=128){
    int i=idx>>6, c=idx&63;
    float acc = 0.f;
    #pragma unroll
    for(int j=0;j<NC;j++) acc += wig[j*26+i]*msgw[j*64+c];
    atomicAdd(&ap[idx], acc);
  }
}

// ---------------- node output: proj + rmsnorm2 + FFN ----------------
__global__ void k_node(const float* __restrict__ x, float* __restrict__ out,
                       const float* __restrict__ po, const float* __restrict__ g2w,
                       const float* __restrict__ glw, const float* __restrict__ glb,
                       const float* __restrict__ fw1, const float* __restrict__ fb1,
                       const float* __restrict__ fw2, const float* __restrict__ fb2,
                       const float* __restrict__ tg, const float* __restrict__ fg)
{
  extern __shared__ float sm[];
  float* sPO  = sm;          // 64*64
  float* sGL  = sPO+4096;    // 64*128
  float* sW1  = sGL+8192;    // 64*128
  float* sW2  = sW1+8192;    // 128*64
  float* sTG  = sW2+8192;    // 900
  float* sFG  = sTG+900;     // 900
  float* sGLB = sFG+900;     // 128
  float* sB1  = sGLB+128;    // 128
  float* sB2  = sB1+128;     // 64
  float* sGam = sB2+64;      // 64
  float* sA   = sGam+64;     // 1600
  float* sXN  = sA+1600;     // 1600
  float* sH   = sXN+1600;    // 1600
  float* sRinv= sH+1600;     // 64
  float* sGate= sRinv+64;    // 128
  float* sF1  = sGate+128;   // 3200
  float* sG2  = sF1+3200;    // 4608
  int tid = threadIdx.x;
  for(int i=tid;i<4096;i+=256) sPO[i]=po[i];
  for(int i=tid;i<8192;i+=256){ sGL[i]=glw[i]; sW1[i]=fw1[i]; sW2[i]=fw2[i]; }
  for(int i=tid;i<900;i+=256){ sTG[i]=tg[i]; sFG[i]=fg[i]; }
  if(tid<128){ sGLB[tid]=glb[tid]; sB1[tid]=fb1[tid]; }
  if(tid<64){ sB2[tid]=fb2[tid]; sGam[tid]=g2w[tid]; }
  __syncthreads();

  for(int n=blockIdx.x; n<NN; n+=gridDim.x){
    const float* xp = x + (size_t)n*1600;
    const float* ag = g_agg + (size_t)n*1600;
    for(int i=tid;i<1600;i+=256) sA[i]=ag[i];
    __syncthreads();
    // xn = x + agg @ proj_out
    for(int idx=tid; idx<1600; idx+=256){
      int i=idx>>6, c=idx&63;
      float acc = xp[idx];
      #pragma unroll 8
      for(int k=0;k<64;k++) acc += sA[i*64+k]*sPO[k*64+c];
      sXN[idx] = acc;
    }
    __syncthreads();
    if(tid<64){
      float s = 0.f;
      #pragma unroll
      for(int i=0;i<NC;i++){ float v = sXN[i*64+tid]; s += v*v; }
      sRinv[tid] = rsqrtf(s*(1.f/25.f)+1e-6f)*sGam[tid];
    }
    __syncthreads();
    for(int idx=tid;idx<1600;idx+=256) sH[idx]=sXN[idx]*sRinv[idx&63];
    __syncthreads();
    if(tid<128){
      float acc = sGLB[tid];
      #pragma unroll 8
      for(int c=0;c<64;c++) acc += sH[c]*sGL[c*128+tid];
      sGate[tid]=acc;
    }
    for(int idx=tid; idx<3200; idx+=256){
      int i=idx>>7, f=idx&127;
      float acc = (i==0)? sB1[f] : 0.f;
      #pragma unroll 8
      for(int c=0;c<64;c++) acc += sH[i*64+c]*sW1[c*128+f];
      sF1[idx]=acc;
    }
    __syncthreads();
    for(int idx=tid; idx<4608; idx+=256){
      int g=idx>>7, f=idx&127;
      float acc = 0.f;
      #pragma unroll
      for(int i=0;i<NC;i++) acc += sTG[g*25+i]*sF1[i*128+f];
      sG2[idx]=silu(acc);
    }
    __syncthreads();
    for(int idx=tid; idx<3200; idx+=256){
      int i=idx>>7, f=idx&127;
      float v;
      if(i==0) v = silu(sGate[f]);
      else{
        float acc = 0.f;
        #pragma unroll
        for(int g=0;g<GG;g++) acc += sFG[i*36+g]*sG2[g*128+f];
        v = acc;
      }
      sF1[idx]=v;
    }
    __syncthreads();
    float* op = out + (size_t)n*1600;
    for(int idx=tid; idx<1600; idx+=256){
      int i=idx>>6, c=idx&63;
      float acc = (i==0)? sB2[c] : 0.f;
      #pragma unroll 8
      for(int f=0;f<128;f++) acc += sF1[i*128+f]*sW2[f*64+c];
      op[idx] = sXN[idx]+acc;
    }
    __syncthreads();
  }
}

extern "C" void kernel_launch(void* const* d_in, const int* in_sizes, int n_in,
                              void* d_out, int out_size) {
  const float* x    = (const float*)d_in[0];
  const int*   ei   = (const int*)d_in[1];
  const int*   zn   = (const int*)d_in[2];
  const float* ed   = (const float*)d_in[3];
  const float* wigr = (const float*)d_in[4];
  const float* stab = (const float*)d_in[5];
  const float* ttab = (const float*)d_in[6];
  const float* rw1  = (const float*)d_in[7];
  const float* rb1  = (const float*)d_in[8];
  const float* rw2  = (const float*)d_in[9];
  const float* rb2  = (const float*)d_in[10];
  const float* rw3  = (const float*)d_in[11];
  const float* rb3  = (const float*)d_in[12];
  const float* W1   = (const float*)d_in[13];
  const float* W0e  = (const float*)d_in[14];
  const float* adot = (const float*)d_in[15];
  const float* tg   = (const float*)d_in[16];
  const float* fg   = (const float*)d_in[17];
  const float* po   = (const float*)d_in[18];
  const float* gm1  = (const float*)d_in[19];
  const float* gm2  = (const float*)d_in[20];
  const float* glw  = (const float*)d_in[21];
  const float* glb  = (const float*)d_in[22];
  const float* fw1  = (const float*)d_in[23];
  const float* fb1  = (const float*)d_in[24];
  const float* fw2  = (const float*)d_in[25];
  const float* fb2  = (const float*)d_in[26];
  float* out = (float*)d_out;

  // zero accumulators
  void *pagg, *pamax, *pasum;
  cudaGetSymbolAddress(&pagg,  g_agg);
  cudaGetSymbolAddress(&pamax, g_amax);
  cudaGetSymbolAddress(&pasum, g_asum);
  cudaMemsetAsync(pagg,  0, (size_t)NN*NC*CC*sizeof(float));
  cudaMemsetAsync(pamax, 0, (size_t)NN*NHEADS*sizeof(unsigned));
  cudaMemsetAsync(pasum, 0, (size_t)NN*NHEADS*sizeof(float));

  const int RAD_SMEM  = 211456;
  const int EDGE_SMEM = 185928;
  const int NODE_SMEM = 174624;
  cudaFuncSetAttribute(k_rad,  cudaFuncAttributeMaxDynamicSharedMemorySize, RAD_SMEM);
  cudaFuncSetAttribute(k_edge, cudaFuncAttributeMaxDynamicSharedMemorySize, EDGE_SMEM);
  cudaFuncSetAttribute(k_node, cudaFuncAttributeMaxDynamicSharedMemorySize, NODE_SMEM);

  k_rms1<<<(NN+3)/4, dim3(64,4)>>>(x, gm1);
  k_rad<<<296, 256, RAD_SMEM>>>(ed, ei, zn, stab, ttab, rw1, rb1, rw2, rb2, rw3, rb3);
  k_edge<<<296, 256, EDGE_SMEM>>>(wigr, ei, W1, W0e, adot, tg, fg);
  k_att<<<(EE*NHEADS+255)/256, 256>>>(ei);
  k_scatter<<<EE, 128>>>(wigr, ei);
  k_node<<<296, 256, NODE_SMEM>>>(x, out, po, gm2, glw, glb, fw1, fb1, fw2, fb2, tg, fg);
}

// round 2
// speedup vs baseline: 1.5296x; 1.5296x over previous
#include <cuda_runtime.h>

#define NN 10000
#define EE 50000
#define NC 25
#define CC 64
#define C2 128
#define NHEADS 8
#define ACH 16
#define VCH 8
#define FFD 128
#define GG 36

__constant__ int c_lof[NC] = {0,1,1,1,2,2,2,2,2,3,3,3,3,3,3,3,4,4,4,4,4,4,4,4,4};

// Scratch (device globals: allocation-free rule)
__device__ float    g_h[(size_t)NN*NC*CC];        // rmsnorm1 output
__device__ float    g_r[(size_t)EE*5*C2];         // radial MLP output
__device__ float    g_msg[(size_t)EE*NC*CC];      // per-edge messages
__device__ float    g_alpha[EE*NHEADS];
__device__ float    g_ez[EE*NHEADS];
__device__ unsigned g_amax[NN*NHEADS];
__device__ float    g_asum[NN*NHEADS];
__device__ float    g_agg[(size_t)NN*NC*CC];

__device__ __forceinline__ float silu(float x){ return x/(1.f+__expf(-x)); }

__device__ __forceinline__ unsigned enc_f(float x){
  unsigned b = __float_as_uint(x);
  return (b & 0x80000000u) ? ~b : (b | 0x80000000u);
}
__device__ __forceinline__ float dec_f(unsigned u){
  unsigned b = (u & 0x80000000u) ? (u & 0x7FFFFFFFu) : ~u;
  return __uint_as_float(b);
}

// ---------------- rmsnorm over coef axis ----------------
__global__ void k_rms1(const float* __restrict__ x, const float* __restrict__ gamma){
  int n = blockIdx.x*4 + threadIdx.y;
  if(n >= NN) return;
  int c = threadIdx.x;
  const float* xp = x + (size_t)n*1600 + c;
  float s = 0.f;
  #pragma unroll
  for(int i=0;i<NC;i++){ float v = xp[i*64]; s += v*v; }
  float gm = rsqrtf(s*(1.f/25.f) + 1e-6f) * gamma[c];
  float* hp = g_h + (size_t)n*1600 + c;
  #pragma unroll
  for(int i=0;i<NC;i++) hp[i*64] = xp[i*64]*gm;
}

// ---------------- radial MLP (weights SMEM-resident) ----------------
__global__ void k_rad(const float* __restrict__ ed, const int* __restrict__ ei,
                      const int* __restrict__ zn,
                      const float* __restrict__ st, const float* __restrict__ tt,
                      const float* __restrict__ w1, const float* __restrict__ b1,
                      const float* __restrict__ w2, const float* __restrict__ b2,
                      const float* __restrict__ w3, const float* __restrict__ b3)
{
  extern __shared__ float sm[];
  float* sw1 = sm;          // 96*64
  float* sw2 = sw1 + 6144;  // 64*64
  float* sw3 = sw2 + 4096;  // 64*640
  float* sb1 = sw3 + 40960; // 64
  float* sb2 = sb1 + 64;    // 64
  float* sb3 = sb2 + 64;    // 640
  float* ef  = sb3 + 640;   // 4*96
  float* h1  = ef + 384;    // 4*64
  float* h2  = h1 + 256;    // 4*64
  int tid = threadIdx.x;
  for(int i=tid;i<6144;i+=256)  sw1[i]=w1[i];
  for(int i=tid;i<4096;i+=256)  sw2[i]=w2[i];
  for(int i=tid;i<40960;i+=256) sw3[i]=w3[i];
  if(tid<64){ sb1[tid]=b1[tid]; sb2[tid]=b2[tid]; }
  for(int i=tid;i<640;i+=256)   sb3[i]=b3[i];
  __syncthreads();

  int grp = tid>>6, t = tid&63;
  int iters = (EE + (int)gridDim.x*4 - 1)/((int)gridDim.x*4);
  for(int it=0; it<iters; it++){
    int e = (it*(int)gridDim.x + (int)blockIdx.x)*4 + grp;
    bool valid = (e < EE);
    if(valid && t<32){
      int src = ei[e], dst = ei[EE+e];
      ef[grp*96+t]      = ed[(size_t)e*32+t];
      ef[grp*96+32+t]   = st[zn[src]*32+t];
      ef[grp*96+64+t]   = tt[zn[dst]*32+t];
    }
    __syncthreads();
    if(valid){
      float acc = sb1[t];
      #pragma unroll 8
      for(int k=0;k<96;k++) acc += ef[grp*96+k]*sw1[k*64+t];
      h1[grp*64+t] = silu(acc);
    }
    __syncthreads();
    if(valid){
      float acc = sb2[t];
      #pragma unroll 8
      for(int k=0;k<64;k++) acc += h1[grp*64+k]*sw2[k*64+t];
      h2[grp*64+t] = silu(acc);
    }
    __syncthreads();
    if(valid){
      float* rp = g_r + (size_t)e*640;
      for(int o=t;o<640;o+=64){
        float acc = sb3[o];
        #pragma unroll 8
        for(int k=0;k<64;k++) acc += h2[grp*64+k]*sw3[k*640+o];
        rp[o] = acc;
      }
    }
    __syncthreads();
  }
}

// ---------------- main per-edge kernel ----------------
__global__ void k_edge(const float* __restrict__ wigner, const int* __restrict__ ei,
                       const float* __restrict__ W1, const float* __restrict__ W0,
                       const float* __restrict__ adot, const float* __restrict__ tg,
                       const float* __restrict__ fg)
{
  extern __shared__ float sm[];
  float* sW1   = sm;            // 128*64
  float* sW0   = sW1 + 8192;    // 128*192
  float* sTG   = sW0 + 24576;   // 36*25
  float* sFG   = sTG + 900;     // 25*36
  float* sAD   = sFG + 900;     // 8*16
  float* wig   = sAD + 128;     // 25*26 (padded)
  float* cat   = wig + 650;     // 25*128
  float* xe    = cat + 3200;    // 25*128
  float* rr    = xe + 3200;     // 640
  float* extra = rr + 640;      // 192
  float* smsg  = extra + 192;   // 25*64
  float* sgrid = smsg + 1600;   // 36*64
  int tid = threadIdx.x;
  for(int i=tid;i<8192;i+=256)  sW1[i]=W1[i];
  for(int i=tid;i<24576;i+=256) sW0[i]=W0[i];
  for(int i=tid;i<900;i+=256){ sTG[i]=tg[i]; sFG[i]=fg[i]; }
  if(tid<128) sAD[tid]=adot[tid];
  __syncthreads();

  for(int e=blockIdx.x; e<EE; e+=gridDim.x){
    int src = ei[e], dst = ei[EE+e];
    const float* wp = wigner + (size_t)e*625;
    for(int i=tid;i<625;i+=256) wig[(i/25)*26 + (i%25)] = wp[i];
    const float* hs = g_h + (size_t)src*1600;
    const float* hd = g_h + (size_t)dst*1600;
    for(int i=tid;i<3200;i+=256){
      int j=i>>7, c=i&127;
      cat[i] = (c<64) ? hs[j*64+c] : hd[j*64+c-64];
    }
    const float* rp = g_r + (size_t)e*640;
    for(int i=tid;i<640;i+=256) rr[i]=rp[i];
    __syncthreads();

    // xe = (wig @ cat) * r[EXPAND]
    for(int idx=tid; idx<3200; idx+=256){
      int i=idx>>7, c=idx&127;
      const float* wr = &wig[i*26];
      float acc = 0.f;
      #pragma unroll
      for(int j=0;j<NC;j++) acc += wr[j]*cat[j*128+c];
      xe[idx] = acc * rr[c_lof[i]*128+c];
    }
    __syncthreads();

    // extra = xe[0,:] @ W0_extra (192 outputs)
    if(tid<192){
      float acc = 0.f;
      #pragma unroll 8
      for(int c=0;c<128;c++) acc += xe[c]*sW0[c*192+tid];
      extra[tid] = acc;
    }
    __syncthreads();

    // alpha + segment max
    if(tid<8){
      float acc = 0.f;
      #pragma unroll
      for(int a=0;a<ACH;a++){ float v = extra[tid*16+a]; acc += silu(v)*sAD[tid*16+a]; }
      g_alpha[e*8+tid] = acc;
      atomicMax(&g_amax[dst*8+tid], enc_f(acc));
    }
    // msg = xe @ W1
    for(int idx=tid; idx<1600; idx+=256){
      int i=idx>>6, h=idx&63;
      float acc = 0.f;
      #pragma unroll 8
      for(int c=0;c<128;c++) acc += xe[i*128+c]*sW1[c*64+h];
      smsg[idx] = acc;
    }
    __syncthreads();
    // grid = silu(to_grid @ msg)
    for(int idx=tid; idx<2304; idx+=256){
      int g=idx>>6, h=idx&63;
      float acc = 0.f;
      #pragma unroll
      for(int i=0;i<NC;i++) acc += sTG[g*25+i]*smsg[i*64+h];
      sgrid[idx] = silu(acc);
    }
    __syncthreads();
    // xg = from_grid @ grid, row 0 := silu(gate)
    float* op = g_msg + (size_t)e*1600;
    for(int idx=tid; idx<1600; idx+=256){
      int i=idx>>6, h=idx&63;
      float v;
      if(i==0) v = silu(extra[128+h]);
      else {
        float acc = 0.f;
        #pragma unroll
        for(int g=0;g<GG;g++) acc += sFG[i*36+g]*sgrid[g*64+h];
        v = acc;
      }
      op[idx] = v;
    }
    __syncthreads();
  }
}

// ---------------- softmax pass 2 ----------------
__global__ void k_att(const int* __restrict__ ei){
  int idx = blockIdx.x*blockDim.x + threadIdx.x;
  if(idx >= EE*NHEADS) return;
  int e = idx>>3, h = idx&7;
  int dst = ei[EE+e];
  float am = dec_f(g_amax[dst*8+h]);
  float ez = __expf(g_alpha[idx]-am);
  g_ez[idx] = ez;
  atomicAdd(&g_asum[dst*8+h], ez);
}

// ---------------- weight + wigner^T + scatter ----------------
__global__ void k_scatter(const float* __restrict__ wigner, const int* __restrict__ ei){
  __shared__ float wig[650];
  __shared__ float msgw[1600];
  __shared__ float wgt[8];
  int e = blockIdx.x;
  int tid = threadIdx.x;
  int dst = ei[EE+e];
  if(tid<8){
    float z = g_ez[e*8+tid];
    float s = g_asum[dst*8+tid];
    wgt[tid] = z/(s+1e-8f);
  }
  const float* wp = wigner + (size_t)e*625;
  for(int i=tid;i<625;i+=128) wig[(i/25)*26+(i%25)] = wp[i];
  __syncthreads();
  const float* mp = g_msg + (size_t)e*1600;
  for(int i=tid;i<1600;i+=128){
    int c = i&63;
    msgw[i] = mp[i]*wgt[c>>3];
  }
  __syncthreads();
  float* ap = g_agg + (size_t)dst*1600;
  for(int idx=tid; idx<1600; idx+=128){
    int i=idx>>6, c=idx&63;
    float acc = 0.f;
    #pragma unroll
    for(int j=0;j<NC;j++) acc += wig[j*26+i]*msgw[j*64+c];
    atomicAdd(&ap[idx], acc);
  }
}

// ---------------- node output: proj + rmsnorm2 + FFN ----------------
__global__ void k_node(const float* __restrict__ x, float* __restrict__ out,
                       const float* __restrict__ po, const float* __restrict__ g2w,
                       const float* __restrict__ glw, const float* __restrict__ glb,
                       const float* __restrict__ fw1, const float* __restrict__ fb1,
                       const float* __restrict__ fw2, const float* __restrict__ fb2,
                       const float* __restrict__ tg, const float* __restrict__ fg)
{
  extern __shared__ float sm[];
  float* sPO  = sm;          // 64*64
  float* sGL  = sPO+4096;    // 64*128
  float* sW1  = sGL+8192;    // 64*128
  float* sW2  = sW1+8192;    // 128*64
  float* sTG  = sW2+8192;    // 900
  float* sFG  = sTG+900;     // 900
  float* sGLB = sFG+900;     // 128
  float* sB1  = sGLB+128;    // 128
  float* sB2  = sB1+128;     // 64
  float* sGam = sB2+64;      // 64
  float* sA   = sGam+64;     // 1600
  float* sXN  = sA+1600;     // 1600
  float* sH   = sXN+1600;    // 1600
  float* sRinv= sH+1600;     // 64
  float* sGate= sRinv+64;    // 128
  float* sF1  = sGate+128;   // 3200
  float* sG2  = sF1+3200;    // 4608
  int tid = threadIdx.x;
  for(int i=tid;i<4096;i+=256) sPO[i]=po[i];
  for(int i=tid;i<8192;i+=256){ sGL[i]=glw[i]; sW1[i]=fw1[i]; sW2[i]=fw2[i]; }
  for(int i=tid;i<900;i+=256){ sTG[i]=tg[i]; sFG[i]=fg[i]; }
  if(tid<128){ sGLB[tid]=glb[tid]; sB1[tid]=fb1[tid]; }
  if(tid<64){ sB2[tid]=fb2[tid]; sGam[tid]=g2w[tid]; }
  __syncthreads();

  for(int n=blockIdx.x; n<NN; n+=gridDim.x){
    const float* xp = x + (size_t)n*1600;
    const float* ag = g_agg + (size_t)n*1600;
    for(int i=tid;i<1600;i+=256) sA[i]=ag[i];
    __syncthreads();
    // xn = x + agg @ proj_out
    for(int idx=tid; idx<1600; idx+=256){
      int i=idx>>6, c=idx&63;
      float acc = xp[idx];
      #pragma unroll 8
      for(int k=0;k<64;k++) acc += sA[i*64+k]*sPO[k*64+c];
      sXN[idx] = acc;
    }
    __syncthreads();
    if(tid<64){
      float s = 0.f;
      #pragma unroll
      for(int i=0;i<NC;i++){ float v = sXN[i*64+tid]; s += v*v; }
      sRinv[tid] = rsqrtf(s*(1.f/25.f)+1e-6f)*sGam[tid];
    }
    __syncthreads();
    for(int idx=tid;idx<1600;idx+=256) sH[idx]=sXN[idx]*sRinv[idx&63];
    __syncthreads();
    if(tid<128){
      float acc = sGLB[tid];
      #pragma unroll 8
      for(int c=0;c<64;c++) acc += sH[c]*sGL[c*128+tid];
      sGate[tid]=acc;
    }
    for(int idx=tid; idx<3200; idx+=256){
      int i=idx>>7, f=idx&127;
      float acc = (i==0)? sB1[f] : 0.f;
      #pragma unroll 8
      for(int c=0;c<64;c++) acc += sH[i*64+c]*sW1[c*128+f];
      sF1[idx]=acc;
    }
    __syncthreads();
    for(int idx=tid; idx<4608; idx+=256){
      int g=idx>>7, f=idx&127;
      float acc = 0.f;
      #pragma unroll
      for(int i=0;i<NC;i++) acc += sTG[g*25+i]*sF1[i*128+f];
      sG2[idx]=silu(acc);
    }
    __syncthreads();
    for(int idx=tid; idx<3200; idx+=256){
      int i=idx>>7, f=idx&127;
      float v;
      if(i==0) v = silu(sGate[f]);
      else{
        float acc = 0.f;
        #pragma unroll
        for(int g=0;g<GG;g++) acc += sFG[i*36+g]*sG2[g*128+f];
        v = acc;
      }
      sF1[idx]=v;
    }
    __syncthreads();
    float* op = out + (size_t)n*1600;
    for(int idx=tid; idx<1600; idx+=256){
      int i=idx>>6, c=idx&63;
      float acc = (i==0)? sB2[c] : 0.f;
      #pragma unroll 8
      for(int f=0;f<128;f++) acc += sF1[i*128+f]*sW2[f*64+c];
      op[idx] = sXN[idx]+acc;
    }
    __syncthreads();
  }
}

extern "C" void kernel_launch(void* const* d_in, const int* in_sizes, int n_in,
                              void* d_out, int out_size) {
  const float* x    = (const float*)d_in[0];
  const int*   ei   = (const int*)d_in[1];
  const int*   zn   = (const int*)d_in[2];
  const float* ed   = (const float*)d_in[3];
  const float* wigr = (const float*)d_in[4];
  const float* stab = (const float*)d_in[5];
  const float* ttab = (const float*)d_in[6];
  const float* rw1  = (const float*)d_in[7];
  const float* rb1  = (const float*)d_in[8];
  const float* rw2  = (const float*)d_in[9];
  const float* rb2  = (const float*)d_in[10];
  const float* rw3  = (const float*)d_in[11];
  const float* rb3  = (const float*)d_in[12];
  const float* W1   = (const float*)d_in[13];
  const float* W0e  = (const float*)d_in[14];
  const float* adot = (const float*)d_in[15];
  const float* tg   = (const float*)d_in[16];
  const float* fg   = (const float*)d_in[17];
  const float* po   = (const float*)d_in[18];
  const float* gm1  = (const float*)d_in[19];
  const float* gm2  = (const float*)d_in[20];
  const float* glw  = (const float*)d_in[21];
  const float* glb  = (const float*)d_in[22];
  const float* fw1  = (const float*)d_in[23];
  const float* fb1  = (const float*)d_in[24];
  const float* fw2  = (const float*)d_in[25];
  const float* fb2  = (const float*)d_in[26];
  float* out = (float*)d_out;

  // zero accumulators
  void *pagg, *pamax, *pasum;
  cudaGetSymbolAddress(&pagg,  g_agg);
  cudaGetSymbolAddress(&pamax, g_amax);
  cudaGetSymbolAddress(&pasum, g_asum);
  cudaMemsetAsync(pagg,  0, (size_t)NN*NC*CC*sizeof(float));
  cudaMemsetAsync(pamax, 0, (size_t)NN*NHEADS*sizeof(unsigned));
  cudaMemsetAsync(pasum, 0, (size_t)NN*NHEADS*sizeof(float));

  const int RAD_SMEM  = 211456;
  const int EDGE_SMEM = 185928;
  const int NODE_SMEM = 174624;
  cudaFuncSetAttribute(k_rad,  cudaFuncAttributeMaxDynamicSharedMemorySize, RAD_SMEM);
  cudaFuncSetAttribute(k_edge, cudaFuncAttributeMaxDynamicSharedMemorySize, EDGE_SMEM);
  cudaFuncSetAttribute(k_node, cudaFuncAttributeMaxDynamicSharedMemorySize, NODE_SMEM);

  k_rms1<<<(NN+3)/4, dim3(64,4)>>>(x, gm1);
  k_rad<<<296, 256, RAD_SMEM>>>(ed, ei, zn, stab, ttab, rw1, rb1, rw2, rb2, rw3, rb3);
  k_edge<<<296, 256, EDGE_SMEM>>>(wigr, ei, W1, W0e, adot, tg, fg);
  k_att<<<(EE*NHEADS+255)/256, 256>>>(ei);
  k_scatter<<<EE, 128>>>(wigr, ei);
  k_node<<<296, 256, NODE_SMEM>>>(x, out, po, gm2, glw, glb, fw1, fb1, fw2, fb2, tg, fg);
}

// round 3
// speedup vs baseline: 1.8395x; 1.2027x over previous
#include <cuda_runtime.h>

#define NN 10000
#define EE 50000
#define NC 25

__constant__ int c_lof[NC] = {0,1,1,1,2,2,2,2,2,3,3,3,3,3,3,3,4,4,4,4,4,4,4,4,4};

__device__ float    g_h[(size_t)NN*1600];
__device__ float    g_r[(size_t)EE*640];
__device__ float    g_msg[(size_t)EE*1600];   // rotated messages
__device__ float    g_alpha[EE*8];
__device__ float    g_ez[EE*8];
__device__ unsigned g_amax[NN*8];
__device__ float    g_asum[NN*8];
__device__ int      g_cnt[NN];
__device__ int      g_rp[NN+1];
__device__ int      g_cur[NN];
__device__ int      g_ce[EE];

__device__ __forceinline__ float silu(float x){ return x/(1.f+__expf(-x)); }
__device__ __forceinline__ float4 silu4(float4 v){
  return make_float4(silu(v.x),silu(v.y),silu(v.z),silu(v.w));
}
__device__ __forceinline__ unsigned enc_f(float x){
  unsigned b=__float_as_uint(x); return (b&0x80000000u)?~b:(b|0x80000000u);
}
#define FMA4(a,s,v) { (a).x=fmaf((s),(v).x,(a).x); (a).y=fmaf((s),(v).y,(a).y); \
                      (a).z=fmaf((s),(v).z,(a).z); (a).w=fmaf((s),(v).w,(a).w); }
#define MUL4(a,v)   { (a).x*=(v).x; (a).y*=(v).y; (a).z*=(v).z; (a).w*=(v).w; }
#define Z4 make_float4(0.f,0.f,0.f,0.f)

// ---------------- rmsnorm1 ----------------
__global__ void k_rms1(const float* __restrict__ x, const float* __restrict__ gamma){
  int n = blockIdx.x*4 + threadIdx.y;
  if(n >= NN) return;
  int c = threadIdx.x;
  const float* xp = x + (size_t)n*1600 + c;
  float s = 0.f;
  #pragma unroll
  for(int i=0;i<NC;i++){ float v = xp[i*64]; s += v*v; }
  float gm = rsqrtf(s*(1.f/25.f) + 1e-6f) * gamma[c];
  float* hp = g_h + (size_t)n*1600 + c;
  #pragma unroll
  for(int i=0;i<NC;i++) hp[i*64] = xp[i*64]*gm;
}

// ---------------- CSR build ----------------
__global__ void k_count(const int* __restrict__ ei){
  int e = blockIdx.x*256 + threadIdx.x;
  if(e < EE) atomicAdd(&g_cnt[ei[EE+e]], 1);
}
__global__ void k_scan(){
  __shared__ int ps[1024];
  int t = threadIdx.x;
  int v[10]; int s = 0;
  #pragma unroll
  for(int m=0;m<10;m++){ int i=t*10+m; int c=(i<NN)? g_cnt[i]:0; v[m]=s; s+=c; }
  ps[t]=s; __syncthreads();
  for(int off=1; off<1024; off<<=1){
    int val=(t>=off)? ps[t-off]:0; __syncthreads();
    ps[t]+=val; __syncthreads();
  }
  int excl=(t>0)? ps[t-1]:0;
  #pragma unroll
  for(int m=0;m<10;m++){
    int i=t*10+m;
    if(i<NN){ int o=excl+v[m]; g_rp[i]=o; g_cur[i]=o; }
  }
  if(t==0) g_rp[NN]=EE;
}
__global__ void k_fill(const int* __restrict__ ei){
  int e = blockIdx.x*256 + threadIdx.x;
  if(e < EE) g_ce[atomicAdd(&g_cur[ei[EE+e]],1)] = e;
}

// ---------------- radial MLP ----------------
__global__ void k_rad(const float* __restrict__ ed, const int* __restrict__ ei,
                      const int* __restrict__ zn,
                      const float* __restrict__ st, const float* __restrict__ tt,
                      const float* __restrict__ w1, const float* __restrict__ b1,
                      const float* __restrict__ w2, const float* __restrict__ b2,
                      const float* __restrict__ w3, const float* __restrict__ b3)
{
  extern __shared__ float sm[];
  float* sw1=sm; float* sw2=sw1+6144; float* sw3=sw2+4096;
  float* sb1=sw3+40960; float* sb2=sb1+64; float* sb3=sb2+64;
  float* ef=sb3+640; float* h1=ef+384; float* h2=h1+256;
  int tid=threadIdx.x;
  for(int i=tid;i<6144;i+=256)  sw1[i]=w1[i];
  for(int i=tid;i<4096;i+=256)  sw2[i]=w2[i];
  for(int i=tid;i<40960;i+=256) sw3[i]=w3[i];
  if(tid<64){ sb1[tid]=b1[tid]; sb2[tid]=b2[tid]; }
  for(int i=tid;i<640;i+=256)   sb3[i]=b3[i];
  __syncthreads();
  int grp=tid>>6, t=tid&63;
  int iters=(EE+(int)gridDim.x*4-1)/((int)gridDim.x*4);
  for(int it=0; it<iters; it++){
    int e=(it*(int)gridDim.x+(int)blockIdx.x)*4+grp;
    bool valid=(e<EE);
    if(valid && t<32){
      int src=ei[e], dst=ei[EE+e];
      ef[grp*96+t]   =ed[(size_t)e*32+t];
      ef[grp*96+32+t]=st[zn[src]*32+t];
      ef[grp*96+64+t]=tt[zn[dst]*32+t];
    }
    __syncthreads();
    if(valid){
      float acc=sb1[t];
      #pragma unroll 8
      for(int k=0;k<96;k++) acc=fmaf(ef[grp*96+k],sw1[k*64+t],acc);
      h1[grp*64+t]=silu(acc);
    }
    __syncthreads();
    if(valid){
      float acc=sb2[t];
      #pragma unroll 8
      for(int k=0;k<64;k++) acc=fmaf(h1[grp*64+k],sw2[k*64+t],acc);
      h2[grp*64+t]=silu(acc);
    }
    __syncthreads();
    if(valid){
      float* rp=g_r+(size_t)e*640;
      for(int o=t;o<640;o+=64){
        float acc=sb3[o];
        #pragma unroll 8
        for(int k=0;k<64;k++) acc=fmaf(h2[grp*64+k],sw3[k*640+o],acc);
        rp[o]=acc;
      }
    }
    __syncthreads();
  }
}

// ---------------- per-edge kernel (fused xe/msg/s2act/wigner^T) ----------------
__global__ __launch_bounds__(256,1)
void k_edge(const float* __restrict__ wigner, const int* __restrict__ ei,
            const float* __restrict__ W1, const float* __restrict__ W0,
            const float* __restrict__ adot, const float* __restrict__ tg,
            const float* __restrict__ fg)
{
  extern __shared__ float sm[];
  float* sW1   = sm;            // [c*64+h] 8192
  float* sW0   = sW1+8192;      // transposed [o*128+c] 24576
  float* sTG   = sW0+24576;     // [g*25+i] 900
  float* sFG   = sTG+900;       // [i*36+g] 900
  float* sAD   = sFG+900;       // 128
  float* swig  = sAD+128;       // [a*28+b] 700
  float* scat  = swig+700;      // [j*128+c] 3200
  float* srr   = scat+3200;     // 640
  float* sxe   = srr+640;       // 3200
  float* sextra= sxe+3200;      // 192
  float* smsg  = sextra+192;    // 1600
  float* sgrid = smsg+1600;     // 2304
  float* smact = sgrid+2304;    // 1600
  int tid=threadIdx.x;
  for(int i=tid;i<8192;i+=256) sW1[i]=W1[i];
  for(int i=tid;i<24576;i+=256){ int o=i>>7,c=i&127; sW0[i]=W0[c*192+o]; }
  for(int i=tid;i<900;i+=256){ sTG[i]=tg[i]; sFG[i]=fg[i]; }
  if(tid<128) sAD[tid]=adot[tid];
  __syncthreads();

  int c4=tid&31, rg8=tid>>5;     // phase1 layout
  int h4=tid&15, rg16=tid>>4;    // phase3/5/6 layout

  for(int e=blockIdx.x; e<EE; e+=gridDim.x){
    int src=ei[e], dst=ei[EE+e];
    const float* wp=wigner+(size_t)e*625;
    for(int i=tid;i<625;i+=256) swig[(i/25)*28+(i%25)]=wp[i];
    const float4* hs=(const float4*)(g_h+(size_t)src*1600);
    const float4* hd=(const float4*)(g_h+(size_t)dst*1600);
    float4* cat4=(float4*)scat;
    for(int i=tid;i<800;i+=256){ int j=i>>5,q=i&31; cat4[i]=(q<16)?hs[j*16+q]:hd[j*16+q-16]; }
    const float4* rp4=(const float4*)(g_r+(size_t)e*640);
    float4* srr4=(float4*)srr;
    for(int i=tid;i<160;i+=256) srr4[i]=rp4[i];
    __syncthreads();

    // xe = (wig @ cat) * r[EXPAND]
    {
      const float4* catp=(const float4*)scat;
      const float4* r4=(const float4*)srr;
      float4* xe4=(float4*)sxe;
      int r0=rg8, r1=rg8+8, r2=rg8+16;
      float4 a0=Z4,a1=Z4,a2=Z4,a3=Z4;
      #pragma unroll
      for(int j4=0;j4<6;j4++){
        float4 w0=*(const float4*)&swig[r0*28+j4*4];
        float4 w1v=*(const float4*)&swig[r1*28+j4*4];
        float4 w2v=*(const float4*)&swig[r2*28+j4*4];
        float4 w3v=*(const float4*)&swig[24*28+j4*4];
        #pragma unroll
        for(int t=0;t<4;t++){
          float4 cv=catp[(j4*4+t)*32+c4];
          FMA4(a0,((const float*)&w0)[t],cv);
          FMA4(a1,((const float*)&w1v)[t],cv);
          FMA4(a2,((const float*)&w2v)[t],cv);
          if(rg8==0) FMA4(a3,((const float*)&w3v)[t],cv);
        }
      }
      { float4 cv=catp[24*32+c4];
        FMA4(a0,swig[r0*28+24],cv); FMA4(a1,swig[r1*28+24],cv); FMA4(a2,swig[r2*28+24],cv);
        if(rg8==0) FMA4(a3,swig[24*28+24],cv);
      }
      float4 rv;
      rv=r4[c_lof[r0]*32+c4]; MUL4(a0,rv); xe4[r0*32+c4]=a0;
      rv=r4[c_lof[r1]*32+c4]; MUL4(a1,rv); xe4[r1*32+c4]=a1;
      rv=r4[c_lof[r2]*32+c4]; MUL4(a2,rv); xe4[r2*32+c4]=a2;
      if(rg8==0){ rv=r4[4*32+c4]; MUL4(a3,rv); xe4[24*32+c4]=a3; }
    }
    __syncthreads();

    // extra = xe[0,:] @ W0_extra
    if(tid<192){
      const float4* x0=(const float4*)sxe;
      const float4* w=(const float4*)(sW0+tid*128);
      float4 acc=Z4;
      #pragma unroll 8
      for(int k=0;k<32;k++){ float4 xv=x0[k], wv=w[k]; acc.x=fmaf(xv.x,wv.x,acc.x); acc.y=fmaf(xv.y,wv.y,acc.y); acc.z=fmaf(xv.z,wv.z,acc.z); acc.w=fmaf(xv.w,wv.w,acc.w); }
      sextra[tid]=acc.x+acc.y+acc.z+acc.w;
    }
    __syncthreads();

    // alpha + segment max
    if(tid<8){
      float acc=0.f;
      #pragma unroll
      for(int a=0;a<16;a++){ float v=sextra[tid*16+a]; acc=fmaf(silu(v),sAD[tid*16+a],acc); }
      g_alpha[e*8+tid]=acc;
      atomicMax(&g_amax[dst*8+tid], enc_f(acc));
    }
    // msg = xe @ W1
    {
      int r0=rg16, r1=rg16+16; bool v1=(r1<25);
      const float4* x0=(const float4*)(sxe+r0*128);
      const float4* x1=(const float4*)(sxe+(v1?r1:0)*128);
      const float4* w4=(const float4*)sW1;
      float4 a0=Z4,a1=Z4;
      #pragma unroll 8
      for(int ci=0;ci<32;ci++){
        float4 xv0=x0[ci], xv1=x1[ci];
        #pragma unroll
        for(int t=0;t<4;t++){
          float4 wv=w4[(ci*4+t)*16+h4];
          FMA4(a0,((const float*)&xv0)[t],wv);
          FMA4(a1,((const float*)&xv1)[t],wv);
        }
      }
      ((float4*)smsg)[r0*16+h4]=a0;
      if(v1) ((float4*)smsg)[r1*16+h4]=a1;
    }
    __syncthreads();

    // grid = silu(to_grid @ msg)
    {
      int g0=rg16, g1=rg16+16, g2=rg16+32; bool v2=(g2<36);
      const float4* m4=(const float4*)smsg;
      float4* gr4=(float4*)sgrid;
      float4 a0=Z4,a1=Z4,a2=Z4;
      #pragma unroll
      for(int i=0;i<25;i++){
        float4 mv=m4[i*16+h4];
        FMA4(a0,sTG[g0*25+i],mv);
        FMA4(a1,sTG[g1*25+i],mv);
        if(v2) FMA4(a2,sTG[g2*25+i],mv);
      }
      gr4[g0*16+h4]=silu4(a0);
      gr4[g1*16+h4]=silu4(a1);
      if(v2) gr4[g2*16+h4]=silu4(a2);
    }
    __syncthreads();

    // mact = [silu(gate); from_grid @ grid]
    {
      int r0=rg16, r1=rg16+16; bool v1=(r1<25);
      const float4* gr4=(const float4*)sgrid;
      float4 a0=Z4,a1=Z4;
      #pragma unroll 6
      for(int g=0;g<36;g++){
        float4 gv=gr4[g*16+h4];
        if(rg16>0) FMA4(a0,sFG[r0*36+g],gv);
        if(v1)     FMA4(a1,sFG[r1*36+g],gv);
      }
      if(rg16==0) a0=silu4(((const float4*)(sextra+128))[h4]);
      ((float4*)smact)[r0*16+h4]=a0;
      if(v1) ((float4*)smact)[r1*16+h4]=a1;
    }
    __syncthreads();

    // rotated = wig^T @ mact -> global
    {
      int r0=rg16, r1=rg16+16; bool v1=(r1<25);
      const float4* m4=(const float4*)smact;
      float4 a0=Z4,a1=Z4;
      #pragma unroll
      for(int j=0;j<25;j++){
        float4 mv=m4[j*16+h4];
        FMA4(a0,swig[j*28+r0],mv);
        if(v1) FMA4(a1,swig[j*28+r1],mv);
      }
      float4* op=(float4*)(g_msg+(size_t)e*1600);
      op[r0*16+h4]=a0;
      if(v1) op[r1*16+h4]=a1;
    }
    __syncthreads();
  }
}

// ---------------- softmax pass 2 ----------------
__global__ void k_att(const int* __restrict__ ei){
  int idx=blockIdx.x*blockDim.x+threadIdx.x;
  if(idx>=EE*8) return;
  int e=idx>>3, h=idx&7;
  int dst=ei[EE+e];
  unsigned u=g_amax[dst*8+h];
  unsigned b=(u&0x80000000u)?(u&0x7FFFFFFFu):~u;
  float am=__uint_as_float(b);
  float ez=__expf(g_alpha[idx]-am);
  g_ez[idx]=ez;
  atomicAdd(&g_asum[dst*8+h],ez);
}

// ---------------- node: gather + proj + rmsnorm2 + FFN ----------------
__global__ __launch_bounds__(256,1)
void k_node(const float* __restrict__ x, float* __restrict__ out,
            const float* __restrict__ po, const float* __restrict__ g2w,
            const float* __restrict__ glw, const float* __restrict__ glb,
            const float* __restrict__ fw1, const float* __restrict__ fb1,
            const float* __restrict__ fw2, const float* __restrict__ fb2,
            const float* __restrict__ tg, const float* __restrict__ fg)
{
  extern __shared__ float sm[];
  float* sPO  = sm;           // [k*64+c] 4096
  float* sGL  = sPO+4096;     // [c*128+f] 8192
  float* sW1f = sGL+8192;     // [c*128+f] 8192
  float* sW2  = sW1f+8192;    // [f*64+c] 8192
  float* sTG  = sW2+8192;     // 900
  float* sFG  = sTG+900;      // 900
  float* sGLB = sFG+900;      // 128
  float* sB1  = sGLB+128;     // 128
  float* sB2  = sB1+128;      // 64
  float* sGam = sB2+64;       // 64
  float* sWinv= sGam+64;      // 8
  float* sA   = sWinv+8;      // 1600
  float* sXN  = sA+1600;      // 1600
  float* sH   = sXN+1600;     // 1600
  float* sGate= sH+1600;      // 128
  float* sF1  = sGate+128;    // 3200
  float* sG2  = sF1+3200;     // 4608
  int tid=threadIdx.x;
  for(int i=tid;i<4096;i+=256) sPO[i]=po[i];
  for(int i=tid;i<8192;i+=256){ sGL[i]=glw[i]; sW1f[i]=fw1[i]; sW2[i]=fw2[i]; }
  for(int i=tid;i<900;i+=256){ sTG[i]=tg[i]; sFG[i]=fg[i]; }
  if(tid<128){ sGLB[tid]=glb[tid]; sB1[tid]=fb1[tid]; }
  if(tid<64){ sB2[tid]=fb2[tid]; sGam[tid]=g2w[tid]; }
  __syncthreads();

  int c4=tid&15, rg=tid>>4;    // 25-row layouts
  int f4=tid&31, rg8=tid>>5;   // 128-wide layouts

  for(int n=blockIdx.x; n<NN; n+=gridDim.x){
    int beg=g_rp[n], end=g_rp[n+1];
    float4* sA4=(float4*)sA;
    for(int i=tid;i<400;i+=256) sA4[i]=Z4;
    if(tid<8) sWinv[tid]=1.f/(g_asum[n*8+tid]+1e-8f);
    __syncthreads();
    for(int k=beg;k<end;k++){
      int e=g_ce[k];
      const float4* mp=(const float4*)(g_msg+(size_t)e*1600);
      for(int i=tid;i<400;i+=256){
        float w=g_ez[e*8+((i&15)>>1)]*sWinv[(i&15)>>1];
        float4 v=mp[i];
        float4 a=sA4[i];
        FMA4(a,w,v);
        sA4[i]=a;
      }
    }
    __syncthreads();

    // XN = x + agg @ proj_out
    {
      int r0=rg, r1=rg+16; bool v1=(r1<25);
      const float4* x4=(const float4*)(x+(size_t)n*1600);
      const float4* p4=(const float4*)sPO;
      float4 a0=x4[r0*16+c4];
      float4 a1=v1? x4[r1*16+c4] : Z4;
      #pragma unroll 8
      for(int k=0;k<64;k++){
        float4 wv=p4[k*16+c4];
        FMA4(a0,sA[r0*64+k],wv);
        if(v1) FMA4(a1,sA[r1*64+k],wv);
      }
      ((float4*)sXN)[r0*16+c4]=a0;
      if(v1) ((float4*)sXN)[r1*16+c4]=a1;
    }
    __syncthreads();
    if(tid<64){
      float s=0.f;
      #pragma unroll
      for(int i=0;i<NC;i++){ float v=sXN[i*64+tid]; s=fmaf(v,v,s); }
      sWinv[0]=sWinv[0]; // no-op
      sGate[tid]=rsqrtf(s*(1.f/25.f)+1e-6f)*sGam[tid]; // temp store rinv in sGate[0:64]
    }
    __syncthreads();
    {
      float4* sH4=(float4*)sH;
      const float4* xn4=(const float4*)sXN;
      const float4* rv4=(const float4*)sGate;
      for(int i=tid;i<400;i+=256){ float4 v=xn4[i], r=rv4[i&15]; MUL4(v,r); sH4[i]=v; }
    }
    __syncthreads();
    // gate = h0 @ gl_w + glb  (overwrite sGate after rinv consumed)
    float gacc=0.f;
    if(tid<128){
      gacc=sGLB[tid];
      #pragma unroll 8
      for(int c=0;c<64;c++) gacc=fmaf(sH[c],sGL[c*128+tid],gacc);
    }
    __syncthreads();
    if(tid<128) sGate[tid]=gacc;
    // F1 = h @ ffn_w1 (+b1 row0)
    {
      int r0=rg8, r1=rg8+8, r2=rg8+16;
      const float4* w4=(const float4*)sW1f;
      float4 a0=Z4,a1=Z4,a2=Z4,a3=Z4;
      #pragma unroll 8
      for(int c=0;c<64;c++){
        float4 wv=w4[c*32+f4];
        FMA4(a0,sH[r0*64+c],wv);
        FMA4(a1,sH[r1*64+c],wv);
        FMA4(a2,sH[r2*64+c],wv);
        if(rg8==0) FMA4(a3,sH[24*64+c],wv);
      }
      if(rg8==0){ float4 b=((const float4*)sB1)[f4]; a0.x+=b.x;a0.y+=b.y;a0.z+=b.z;a0.w+=b.w; }
      float4* F4=(float4*)sF1;
      F4[r0*32+f4]=a0; F4[r1*32+f4]=a1; F4[r2*32+f4]=a2;
      if(rg8==0) F4[24*32+f4]=a3;
    }
    __syncthreads();
    // G2 = silu(to_grid @ F1)
    {
      int g0=rg8, g1=rg8+8, g2=rg8+16, g3=rg8+24, g4v=rg8+32; bool v4=(g4v<36);
      const float4* F4=(const float4*)sF1;
      float4* G4=(float4*)sG2;
      float4 a0=Z4,a1=Z4,a2=Z4,a3=Z4,a4=Z4;
      #pragma unroll
      for(int i=0;i<25;i++){
        float4 fv=F4[i*32+f4];
        FMA4(a0,sTG[g0*25+i],fv);
        FMA4(a1,sTG[g1*25+i],fv);
        FMA4(a2,sTG[g2*25+i],fv);
        FMA4(a3,sTG[g3*25+i],fv);
        if(v4) FMA4(a4,sTG[g4v*25+i],fv);
      }
      G4[g0*32+f4]=silu4(a0); G4[g1*32+f4]=silu4(a1);
      G4[g2*32+f4]=silu4(a2); G4[g3*32+f4]=silu4(a3);
      if(v4) G4[g4v*32+f4]=silu4(a4);
    }
    __syncthreads();
    // F1 := [silu(gate); from_grid @ G2]
    {
      int r0=rg8, r1=rg8+8, r2=rg8+16;
      const float4* G4=(const float4*)sG2;
      float4 a0=Z4,a1=Z4,a2=Z4,a3=Z4;
      #pragma unroll 6
      for(int g=0;g<36;g++){
        float4 gv=G4[g*32+f4];
        if(rg8>0) FMA4(a0,sFG[r0*36+g],gv);
        FMA4(a1,sFG[r1*36+g],gv);
        FMA4(a2,sFG[r2*36+g],gv);
        if(rg8==0) FMA4(a3,sFG[24*36+g],gv);
      }
      if(rg8==0) a0=silu4(((const float4*)sGate)[f4]);
      float4* F4=(float4*)sF1;
      F4[r0*32+f4]=a0; F4[r1*32+f4]=a1; F4[r2*32+f4]=a2;
      if(rg8==0) F4[24*32+f4]=a3;
    }
    __syncthreads();
    // out = XN + F1 @ ffn_w2 (+b2 row0)
    {
      int r0=rg, r1=rg+16; bool v1=(r1<25);
      const float4* w4=(const float4*)sW2;
      float4 a0=((const float4*)sXN)[r0*16+c4];
      float4 a1=v1? ((const float4*)sXN)[r1*16+c4] : Z4;
      if(r0==0){ float4 b=((const float4*)sB2)[c4]; a0.x+=b.x;a0.y+=b.y;a0.z+=b.z;a0.w+=b.w; }
      #pragma unroll 8
      for(int f=0;f<128;f++){
        float4 wv=w4[f*16+c4];
        FMA4(a0,sF1[r0*128+f],wv);
        if(v1) FMA4(a1,sF1[r1*128+f],wv);
      }
      float4* op=(float4*)(out+(size_t)n*1600);
      op[r0*16+c4]=a0;
      if(v1) op[r1*16+c4]=a1;
    }
    __syncthreads();
  }
}

extern "C" void kernel_launch(void* const* d_in, const int* in_sizes, int n_in,
                              void* d_out, int out_size) {
  const float* x    = (const float*)d_in[0];
  const int*   ei   = (const int*)d_in[1];
  const int*   zn   = (const int*)d_in[2];
  const float* ed   = (const float*)d_in[3];
  const float* wigr = (const float*)d_in[4];
  const float* stab = (const float*)d_in[5];
  const float* ttab = (const float*)d_in[6];
  const float* rw1  = (const float*)d_in[7];
  const float* rb1  = (const float*)d_in[8];
  const float* rw2  = (const float*)d_in[9];
  const float* rb2  = (const float*)d_in[10];
  const float* rw3  = (const float*)d_in[11];
  const float* rb3  = (const float*)d_in[12];
  const float* W1   = (const float*)d_in[13];
  const float* W0e  = (const float*)d_in[14];
  const float* adot = (const float*)d_in[15];
  const float* tg   = (const float*)d_in[16];
  const float* fg   = (const float*)d_in[17];
  const float* po   = (const float*)d_in[18];
  const float* gm1  = (const float*)d_in[19];
  const float* gm2  = (const float*)d_in[20];
  const float* glw  = (const float*)d_in[21];
  const float* glb  = (const float*)d_in[22];
  const float* fw1  = (const float*)d_in[23];
  const float* fb1  = (const float*)d_in[24];
  const float* fw2  = (const float*)d_in[25];
  const float* fb2  = (const float*)d_in[26];
  float* out = (float*)d_out;

  void *pcnt, *pamax, *pasum;
  cudaGetSymbolAddress(&pcnt,  g_cnt);
  cudaGetSymbolAddress(&pamax, g_amax);
  cudaGetSymbolAddress(&pasum, g_asum);
  cudaMemsetAsync(pcnt,  0, NN*sizeof(int));
  cudaMemsetAsync(pamax, 0, NN*8*sizeof(unsigned));
  cudaMemsetAsync(pasum, 0, NN*8*sizeof(float));

  const int RAD_SMEM  = 52864*4;
  const int EDGE_SMEM = 48132*4;
  const int NODE_SMEM = 43600*4;
  cudaFuncSetAttribute(k_rad,  cudaFuncAttributeMaxDynamicSharedMemorySize, RAD_SMEM);
  cudaFuncSetAttribute(k_edge, cudaFuncAttributeMaxDynamicSharedMemorySize, EDGE_SMEM);
  cudaFuncSetAttribute(k_node, cudaFuncAttributeMaxDynamicSharedMemorySize, NODE_SMEM);

  k_rms1<<<(NN+3)/4, dim3(64,4)>>>(x, gm1);
  k_count<<<(EE+255)/256, 256>>>(ei);
  k_scan<<<1, 1024>>>();
  k_fill<<<(EE+255)/256, 256>>>(ei);
  k_rad<<<296, 256, RAD_SMEM>>>(ed, ei, zn, stab, ttab, rw1, rb1, rw2, rb2, rw3, rb3);
  k_edge<<<296, 256, EDGE_SMEM>>>(wigr, ei, W1, W0e, adot, tg, fg);
  k_att<<<(EE*8+255)/256, 256>>>(ei);
  k_node<<<296, 256, NODE_SMEM>>>(x, out, po, gm2, glw, glb, fw1, fb1, fw2, fb2, tg, fg);
}

// round 5
// speedup vs baseline: 2.4098x; 1.3100x over previous
#include <cuda_runtime.h>

#define NN 10000
#define EE 50000
#define NC 25

__constant__ int c_lof[NC] = {0,1,1,1,2,2,2,2,2,3,3,3,3,3,3,3,4,4,4,4,4,4,4,4,4};

__device__ float    g_h[(size_t)NN*1600];
__device__ float    g_r[(size_t)EE*640];
__device__ float    g_msg[(size_t)EE*1600];
__device__ float    g_alpha[EE*8];
__device__ float    g_ez[EE*8];
__device__ unsigned g_amax[NN*8];
__device__ float    g_asum[NN*8];
__device__ int      g_cnt[NN];
__device__ int      g_rp[NN+1];
__device__ int      g_cur[NN];
__device__ int      g_ce[EE];

__device__ __forceinline__ float silu(float x){ return x/(1.f+__expf(-x)); }
__device__ __forceinline__ float4 silu4(float4 v){
  return make_float4(silu(v.x),silu(v.y),silu(v.z),silu(v.w));
}
__device__ __forceinline__ unsigned enc_f(float x){
  unsigned b=__float_as_uint(x); return (b&0x80000000u)?~b:(b|0x80000000u);
}
#define FMA4(a,s,v) { (a).x=fmaf((s),(v).x,(a).x); (a).y=fmaf((s),(v).y,(a).y); \
                      (a).z=fmaf((s),(v).z,(a).z); (a).w=fmaf((s),(v).w,(a).w); }
#define MUL4(a,v)   { (a).x*=(v).x; (a).y*=(v).y; (a).z*=(v).z; (a).w*=(v).w; }
#define Z4 make_float4(0.f,0.f,0.f,0.f)

// ---------------- rmsnorm1 ----------------
__global__ void k_rms1(const float* __restrict__ x, const float* __restrict__ gamma){
  int n = blockIdx.x*4 + threadIdx.y;
  if(n >= NN) return;
  int c = threadIdx.x;
  const float* xp = x + (size_t)n*1600 + c;
  float s = 0.f;
  #pragma unroll
  for(int i=0;i<NC;i++){ float v = xp[i*64]; s += v*v; }
  float gm = rsqrtf(s*(1.f/25.f) + 1e-6f) * gamma[c];
  float* hp = g_h + (size_t)n*1600 + c;
  #pragma unroll
  for(int i=0;i<NC;i++) hp[i*64] = xp[i*64]*gm;
}

// ---------------- CSR build ----------------
__global__ void k_count(const int* __restrict__ ei){
  int e = blockIdx.x*256 + threadIdx.x;
  if(e < EE) atomicAdd(&g_cnt[ei[EE+e]], 1);
}
__global__ void k_scan(){
  __shared__ int ps[1024];
  int t = threadIdx.x;
  int v[10]; int s = 0;
  #pragma unroll
  for(int m=0;m<10;m++){ int i=t*10+m; int c=(i<NN)? g_cnt[i]:0; v[m]=s; s+=c; }
  ps[t]=s; __syncthreads();
  for(int off=1; off<1024; off<<=1){
    int val=(t>=off)? ps[t-off]:0; __syncthreads();
    ps[t]+=val; __syncthreads();
  }
  int excl=(t>0)? ps[t-1]:0;
  #pragma unroll
  for(int m=0;m<10;m++){
    int i=t*10+m;
    if(i<NN){ int o=excl+v[m]; g_rp[i]=o; g_cur[i]=o; }
  }
  if(t==0) g_rp[NN]=EE;
}
__global__ void k_fill(const int* __restrict__ ei){
  int e = blockIdx.x*256 + threadIdx.x;
  if(e < EE) g_ce[atomicAdd(&g_cur[ei[EE+e]],1)] = e;
}

// ---------------- radial MLP (4 edges/iter, weight-stationary layer3) ----------------
__global__ __launch_bounds__(256,1)
void k_rad(const float* __restrict__ ed, const int* __restrict__ ei,
           const int* __restrict__ zn,
           const float* __restrict__ st, const float* __restrict__ tt,
           const float* __restrict__ w1, const float* __restrict__ b1,
           const float* __restrict__ w2, const float* __restrict__ b2,
           const float* __restrict__ w3, const float* __restrict__ b3)
{
  extern __shared__ float sm[];
  float* sw1=sm; float* sw2=sw1+6144; float* sw3=sw2+4096;
  float* sb1=sw3+40960; float* sb2=sb1+64; float* sb3=sb2+64;
  float* ef=sb3+640; float* h1=ef+384; float* h2=h1+256;
  int tid=threadIdx.x;
  for(int i=tid;i<6144;i+=256)  sw1[i]=w1[i];
  for(int i=tid;i<4096;i+=256)  sw2[i]=w2[i];
  for(int i=tid;i<40960;i+=256) sw3[i]=w3[i];
  if(tid<64){ sb1[tid]=b1[tid]; sb2[tid]=b2[tid]; }
  for(int i=tid;i<640;i+=256)   sb3[i]=b3[i];
  __syncthreads();

  int grp=tid>>6, t=tid&63;
  int q=grp;
  int nm=(q<2)?3:2;
  int m0=q, m1=q+4, m2=q+8;

  int iters=(EE+(int)gridDim.x*4-1)/((int)gridDim.x*4);
  for(int it=0; it<iters; it++){
    int e0=(it*(int)gridDim.x+(int)blockIdx.x)*4;
    int e=e0+grp;
    bool valid=(e<EE);
    if(t<32){
      if(valid){
        int src=ei[e], dst=ei[EE+e];
        ef[grp*96+t]   =ed[(size_t)e*32+t];
        ef[grp*96+32+t]=st[zn[src]*32+t];
        ef[grp*96+64+t]=tt[zn[dst]*32+t];
      } else {
        ef[grp*96+t]=0.f; ef[grp*96+32+t]=0.f; ef[grp*96+64+t]=0.f;
      }
    }
    __syncthreads();
    {
      float acc=sb1[t];
      const float4* ef4=(const float4*)(ef+grp*96);
      #pragma unroll
      for(int k4=0;k4<24;k4++){
        float4 v=ef4[k4];
        acc=fmaf(v.x,sw1[(k4*4+0)*64+t],acc);
        acc=fmaf(v.y,sw1[(k4*4+1)*64+t],acc);
        acc=fmaf(v.z,sw1[(k4*4+2)*64+t],acc);
        acc=fmaf(v.w,sw1[(k4*4+3)*64+t],acc);
      }
      h1[grp*64+t]=silu(acc);
    }
    __syncthreads();
    {
      float acc=sb2[t];
      const float4* h14=(const float4*)(h1+grp*64);
      #pragma unroll
      for(int k4=0;k4<16;k4++){
        float4 v=h14[k4];
        acc=fmaf(v.x,sw2[(k4*4+0)*64+t],acc);
        acc=fmaf(v.y,sw2[(k4*4+1)*64+t],acc);
        acc=fmaf(v.z,sw2[(k4*4+2)*64+t],acc);
        acc=fmaf(v.w,sw2[(k4*4+3)*64+t],acc);
      }
      h2[grp*64+t]=silu(acc);
    }
    __syncthreads();
    { // layer3: weight-stationary over 4 edges
      float a0[4], a1[4], a2[4];
      #pragma unroll
      for(int ee=0;ee<4;ee++){ a0[ee]=sb3[t+64*m0]; a1[ee]=sb3[t+64*m1]; a2[ee]=(nm==3)?sb3[t+64*m2]:0.f; }
      for(int k=0;k<64;k++){
        float hh0=h2[k], hh1=h2[64+k], hh2v=h2[128+k], hh3=h2[192+k];
        float wA=sw3[k*640+t+64*m0];
        float wB=sw3[k*640+t+64*m1];
        a0[0]=fmaf(wA,hh0,a0[0]); a0[1]=fmaf(wA,hh1,a0[1]); a0[2]=fmaf(wA,hh2v,a0[2]); a0[3]=fmaf(wA,hh3,a0[3]);
        a1[0]=fmaf(wB,hh0,a1[0]); a1[1]=fmaf(wB,hh1,a1[1]); a1[2]=fmaf(wB,hh2v,a1[2]); a1[3]=fmaf(wB,hh3,a1[3]);
        if(nm==3){
          float wC=sw3[k*640+t+64*m2];
          a2[0]=fmaf(wC,hh0,a2[0]); a2[1]=fmaf(wC,hh1,a2[1]); a2[2]=fmaf(wC,hh2v,a2[2]); a2[3]=fmaf(wC,hh3,a2[3]);
        }
      }
      #pragma unroll
      for(int ee=0;ee<4;ee++){
        int eo=e0+ee;
        if(eo<EE){
          g_r[(size_t)eo*640+t+64*m0]=a0[ee];
          g_r[(size_t)eo*640+t+64*m1]=a1[ee];
          if(nm==3) g_r[(size_t)eo*640+t+64*m2]=a2[ee];
        }
      }
    }
    __syncthreads();
  }
}

// ---------------- per-edge kernel: 2 edges in flight ----------------
__global__ __launch_bounds__(512,1)
void k_edge(const float* __restrict__ wigner, const int* __restrict__ ei,
            const float* __restrict__ W1, const float* __restrict__ W0,
            const float* __restrict__ adot, const float* __restrict__ tg,
            const float* __restrict__ fg)
{
  extern __shared__ float sm[];
  float* sW1 = sm;          // [c*64+h] 8192
  float* sW0 = sW1+8192;    // transposed [o*128+c] 24576
  float* sTG = sW0+24576;   // 900
  float* sFG = sTG+900;     // 900
  float* sAD = sFG+900;     // 128
  float* pe  = sAD+128;     // 2 * 9532
  int tid=threadIdx.x;
  for(int i=tid;i<8192;i+=512) sW1[i]=W1[i];
  for(int i=tid;i<24576;i+=512){ int o=i>>7,c=i&127; sW0[i]=W0[c*192+o]; }
  for(int i=tid;i<900;i+=512){ sTG[i]=tg[i]; sFG[i]=fg[i]; }
  if(tid<128) sAD[tid]=adot[tid];
  __syncthreads();

  int grp = tid>>8, t = tid&255;
  float* swig  = pe + grp*9532;  // 700
  float* scat  = swig+700;       // 3200 (reused as sgrid)
  float* srr   = scat+3200;      // 640
  float* sxe   = srr+640;        // 3200
  float* sextra= sxe+3200;       // 192
  float* smsg  = sextra+192;     // 1600 (reused as smact)
  float* sgrid = scat;
  float* smact = smsg;

  int c4=t&31, rg8=t>>5;
  int h4=t&15, rg16=t>>4;

  for(int eb=blockIdx.x*2; eb<EE; eb+=gridDim.x*2){
    int e = eb + grp;           // EE even -> always valid
    int src=ei[e], dst=ei[EE+e];
    const float* wp=wigner+(size_t)e*625;
    for(int i=t;i<625;i+=256) swig[(i/25)*28+(i%25)]=wp[i];
    const float4* hs=(const float4*)(g_h+(size_t)src*1600);
    const float4* hd=(const float4*)(g_h+(size_t)dst*1600);
    float4* cat4=(float4*)scat;
    for(int i=t;i<800;i+=256){ int j=i>>5,qq=i&31; cat4[i]=(qq<16)?hs[j*16+qq]:hd[j*16+qq-16]; }
    const float4* rp4=(const float4*)(g_r+(size_t)e*640);
    float4* srr4=(float4*)srr;
    for(int i=t;i<160;i+=256) srr4[i]=rp4[i];
    __syncthreads();

    // xe = (wig @ cat) * r[EXPAND]
    {
      const float4* catp=(const float4*)scat;
      const float4* r4=(const float4*)srr;
      float4* xe4=(float4*)sxe;
      int r0=rg8, r1=rg8+8, r2=rg8+16;
      float4 a0=Z4,a1=Z4,a2=Z4,a3=Z4;
      #pragma unroll
      for(int j4=0;j4<6;j4++){
        float4 w0=*(const float4*)&swig[r0*28+j4*4];
        float4 w1v=*(const float4*)&swig[r1*28+j4*4];
        float4 w2v=*(const float4*)&swig[r2*28+j4*4];
        float4 w3v=*(const float4*)&swig[24*28+j4*4];
        #pragma unroll
        for(int tt2=0;tt2<4;tt2++){
          float4 cv=catp[(j4*4+tt2)*32+c4];
          FMA4(a0,((const float*)&w0)[tt2],cv);
          FMA4(a1,((const float*)&w1v)[tt2],cv);
          FMA4(a2,((const float*)&w2v)[tt2],cv);
          if(rg8==0) FMA4(a3,((const float*)&w3v)[tt2],cv);
        }
      }
      { float4 cv=catp[24*32+c4];
        FMA4(a0,swig[r0*28+24],cv); FMA4(a1,swig[r1*28+24],cv); FMA4(a2,swig[r2*28+24],cv);
        if(rg8==0) FMA4(a3,swig[24*28+24],cv);
      }
      float4 rv;
      rv=r4[c_lof[r0]*32+c4]; MUL4(a0,rv); xe4[r0*32+c4]=a0;
      rv=r4[c_lof[r1]*32+c4]; MUL4(a1,rv); xe4[r1*32+c4]=a1;
      rv=r4[c_lof[r2]*32+c4]; MUL4(a2,rv); xe4[r2*32+c4]=a2;
      if(rg8==0){ rv=r4[4*32+c4]; MUL4(a3,rv); xe4[24*32+c4]=a3; }
    }
    __syncthreads();

    // extra = xe[0,:] @ W0_extra
    if(t<192){
      const float4* x0=(const float4*)sxe;
      const float4* w=(const float4*)(sW0+t*128);
      float4 acc=Z4;
      #pragma unroll 8
      for(int k=0;k<32;k++){ float4 xv=x0[k], wv=w[k];
        acc.x=fmaf(xv.x,wv.x,acc.x); acc.y=fmaf(xv.y,wv.y,acc.y);
        acc.z=fmaf(xv.z,wv.z,acc.z); acc.w=fmaf(xv.w,wv.w,acc.w); }
      sextra[t]=acc.x+acc.y+acc.z+acc.w;
    }
    __syncthreads();

    // alpha + segment max
    if(t<8){
      float acc=0.f;
      #pragma unroll
      for(int a=0;a<16;a++){ float v=sextra[t*16+a]; acc=fmaf(silu(v),sAD[t*16+a],acc); }
      g_alpha[e*8+t]=acc;
      atomicMax(&g_amax[dst*8+t], enc_f(acc));
    }
    // msg = xe @ W1
    {
      int r0=rg16, r1=rg16+16; bool v1=(r1<25);
      const float4* x0=(const float4*)(sxe+r0*128);
      const float4* x1=(const float4*)(sxe+(v1?r1:0)*128);
      const float4* w4=(const float4*)sW1;
      float4 a0=Z4,a1=Z4;
      #pragma unroll 8
      for(int ci=0;ci<32;ci++){
        float4 xv0=x0[ci], xv1=x1[ci];
        #pragma unroll
        for(int tt2=0;tt2<4;tt2++){
          float4 wv=w4[(ci*4+tt2)*16+h4];
          FMA4(a0,((const float*)&xv0)[tt2],wv);
          FMA4(a1,((const float*)&xv1)[tt2],wv);
        }
      }
      ((float4*)smsg)[r0*16+h4]=a0;
      if(v1) ((float4*)smsg)[r1*16+h4]=a1;
    }
    __syncthreads();

    // grid = silu(to_grid @ msg)  (writes scat region)
    {
      int g0=rg16, g1=rg16+16, g2=rg16+32; bool v2=(g2<36);
      const float4* m4=(const float4*)smsg;
      float4* gr4=(float4*)sgrid;
      float4 a0=Z4,a1=Z4,a2=Z4;
      #pragma unroll
      for(int i=0;i<25;i++){
        float4 mv=m4[i*16+h4];
        FMA4(a0,sTG[g0*25+i],mv);
        FMA4(a1,sTG[g1*25+i],mv);
        if(v2) FMA4(a2,sTG[g2*25+i],mv);
      }
      gr4[g0*16+h4]=silu4(a0);
      gr4[g1*16+h4]=silu4(a1);
      if(v2) gr4[g2*16+h4]=silu4(a2);
    }
    __syncthreads();

    // mact = [silu(gate); from_grid @ grid]  (writes smsg region)
    {
      int r0=rg16, r1=rg16+16; bool v1=(r1<25);
      const float4* gr4=(const float4*)sgrid;
      float4 a0=Z4,a1=Z4;
      #pragma unroll 6
      for(int g=0;g<36;g++){
        float4 gv=gr4[g*16+h4];
        if(rg16>0) FMA4(a0,sFG[r0*36+g],gv);
        if(v1)     FMA4(a1,sFG[r1*36+g],gv);
      }
      if(rg16==0) a0=silu4(((const float4*)(sextra+128))[h4]);
      ((float4*)smact)[r0*16+h4]=a0;
      if(v1) ((float4*)smact)[r1*16+h4]=a1;
    }
    __syncthreads();

    // rotated = wig^T @ mact -> global
    {
      int r0=rg16, r1=rg16+16; bool v1=(r1<25);
      const float4* m4=(const float4*)smact;
      float4 a0=Z4,a1=Z4;
      #pragma unroll
      for(int j=0;j<25;j++){
        float4 mv=m4[j*16+h4];
        FMA4(a0,swig[j*28+r0],mv);
        if(v1) FMA4(a1,swig[j*28+r1],mv);
      }
      float4* op=(float4*)(g_msg+(size_t)e*1600);
      op[r0*16+h4]=a0;
      if(v1) op[r1*16+h4]=a1;
    }
    __syncthreads();
  }
}

// ---------------- softmax pass 2 ----------------
__global__ void k_att(const int* __restrict__ ei){
  int idx=blockIdx.x*blockDim.x+threadIdx.x;
  if(idx>=EE*8) return;
  int e=idx>>3, h=idx&7;
  int dst=ei[EE+e];
  unsigned u=g_amax[dst*8+h];
  unsigned b=(u&0x80000000u)?(u&0x7FFFFFFFu):~u;
  float am=__uint_as_float(b);
  float ez=__expf(g_alpha[idx]-am);
  g_ez[idx]=ez;
  atomicAdd(&g_asum[dst*8+h],ez);
}

// ---------------- node: 2 nodes in flight ----------------
__global__ __launch_bounds__(512,1)
void k_node(const float* __restrict__ x, float* __restrict__ out,
            const float* __restrict__ po, const float* __restrict__ g2w,
            const float* __restrict__ glw, const float* __restrict__ glb,
            const float* __restrict__ fw1, const float* __restrict__ fb1,
            const float* __restrict__ fw2, const float* __restrict__ fb2,
            const float* __restrict__ tg, const float* __restrict__ fg)
{
  extern __shared__ float sm[];
  float* sPO  = sm;           // 4096
  float* sGL  = sPO+4096;     // 8192
  float* sW1f = sGL+8192;     // 8192
  float* sW2  = sW1f+8192;    // 8192
  float* sTG  = sW2+8192;     // 900
  float* sFG  = sTG+900;      // 900
  float* sGLB = sFG+900;      // 128
  float* sB1  = sGLB+128;     // 128
  float* sB2  = sB1+128;      // 64
  float* sGam = sB2+64;       // 64
  float* pn   = sGam+64;      // 2 * 11144
  int tid=threadIdx.x;
  for(int i=tid;i<4096;i+=512) sPO[i]=po[i];
  for(int i=tid;i<8192;i+=512){ sGL[i]=glw[i]; sW1f[i]=fw1[i]; sW2[i]=fw2[i]; }
  for(int i=tid;i<900;i+=512){ sTG[i]=tg[i]; sFG[i]=fg[i]; }
  if(tid<128){ sGLB[tid]=glb[tid]; sB1[tid]=fb1[tid]; }
  if(tid<64){ sB2[tid]=fb2[tid]; sGam[tid]=g2w[tid]; }
  __syncthreads();

  int grp=tid>>8, t=tid&255;
  float* sWinv= pn + grp*11144; // 8
  float* sXN  = sWinv+8;        // 1600
  float* sH   = sXN+1600;       // 1600
  float* sGate= sH+1600;        // 128
  float* sF1  = sGate+128;      // 3200
  float* sG2  = sF1+3200;       // 4608 (sA aliased here)
  float* sA   = sG2;

  int c4=t&15, rg=t>>4;
  int f4=t&31, rg8=t>>5;

  for(int nb=blockIdx.x*2; nb<NN; nb+=gridDim.x*2){
    int n = nb + grp;           // NN even -> valid
    int beg=g_rp[n], end=g_rp[n+1];
    float4* sA4=(float4*)sA;
    for(int i=t;i<400;i+=256) sA4[i]=Z4;
    if(t<8) sWinv[t]=1.f/(g_asum[n*8+t]+1e-8f);
    __syncthreads();
    for(int k=beg;k<end;k++){
      int e=g_ce[k];
      const float4* mp=(const float4*)(g_msg+(size_t)e*1600);
      for(int i=t;i<400;i+=256){
        float w=g_ez[e*8+((i&15)>>1)]*sWinv[(i&15)>>1];
        float4 v=mp[i];
        float4 a=sA4[i];
        FMA4(a,w,v);
        sA4[i]=a;
      }
    }
    __syncthreads();

    // XN = x + agg @ proj_out
    {
      int r0=rg, r1=rg+16; bool v1=(r1<25);
      const float4* x4=(const float4*)(x+(size_t)n*1600);
      const float4* p4=(const float4*)sPO;
      float4 a0=x4[r0*16+c4];
      float4 a1=v1? x4[r1*16+c4] : Z4;
      #pragma unroll 8
      for(int k=0;k<64;k++){
        float4 wv=p4[k*16+c4];
        FMA4(a0,sA[r0*64+k],wv);
        if(v1) FMA4(a1,sA[r1*64+k],wv);
      }
      ((float4*)sXN)[r0*16+c4]=a0;
      if(v1) ((float4*)sXN)[r1*16+c4]=a1;
    }
    __syncthreads();
    if(t<64){
      float s=0.f;
      #pragma unroll
      for(int i=0;i<NC;i++){ float v=sXN[i*64+t]; s=fmaf(v,v,s); }
      sGate[t]=rsqrtf(s*(1.f/25.f)+1e-6f)*sGam[t];  // rinv temp
    }
    __syncthreads();
    {
      float4* sH4=(float4*)sH;
      const float4* xn4=(const float4*)sXN;
      const float4* rv4=(const float4*)sGate;
      for(int i=t;i<400;i+=256){ float4 v=xn4[i], r=rv4[i&15]; MUL4(v,r); sH4[i]=v; }
    }
    __syncthreads();
    float gacc=0.f;
    if(t<128){
      gacc=sGLB[t];
      #pragma unroll 8
      for(int c=0;c<64;c++) gacc=fmaf(sH[c],sGL[c*128+t],gacc);
    }
    __syncthreads();
    if(t<128) sGate[t]=gacc;
    // F1 = h @ ffn_w1 (+b1 row0)
    {
      int r0=rg8, r1=rg8+8, r2=rg8+16;
      const float4* w4=(const float4*)sW1f;
      float4 a0=Z4,a1=Z4,a2=Z4,a3=Z4;
      #pragma unroll 8
      for(int c=0;c<64;c++){
        float4 wv=w4[c*32+f4];
        FMA4(a0,sH[r0*64+c],wv);
        FMA4(a1,sH[r1*64+c],wv);
        FMA4(a2,sH[r2*64+c],wv);
        if(rg8==0) FMA4(a3,sH[24*64+c],wv);
      }
      if(rg8==0){ float4 b=((const float4*)sB1)[f4]; a0.x+=b.x;a0.y+=b.y;a0.z+=b.z;a0.w+=b.w; }
      float4* F4=(float4*)sF1;
      F4[r0*32+f4]=a0; F4[r1*32+f4]=a1; F4[r2*32+f4]=a2;
      if(rg8==0) F4[24*32+f4]=a3;
    }
    __syncthreads();
    // G2 = silu(to_grid @ F1)
    {
      int g0=rg8, g1=rg8+8, g2=rg8+16, g3=rg8+24, g4v=rg8+32; bool v4=(g4v<36);
      const float4* F4=(const float4*)sF1;
      float4* G4=(float4*)sG2;
      float4 a0=Z4,a1=Z4,a2=Z4,a3=Z4,a4=Z4;
      #pragma unroll
      for(int i=0;i<25;i++){
        float4 fv=F4[i*32+f4];
        FMA4(a0,sTG[g0*25+i],fv);
        FMA4(a1,sTG[g1*25+i],fv);
        FMA4(a2,sTG[g2*25+i],fv);
        FMA4(a3,sTG[g3*25+i],fv);
        if(v4) FMA4(a4,sTG[g4v*25+i],fv);
      }
      G4[g0*32+f4]=silu4(a0); G4[g1*32+f4]=silu4(a1);
      G4[g2*32+f4]=silu4(a2); G4[g3*32+f4]=silu4(a3);
      if(v4) G4[g4v*32+f4]=silu4(a4);
    }
    __syncthreads();
    // F1 := [silu(gate); from_grid @ G2]
    {
      int r0=rg8, r1=rg8+8, r2=rg8+16;
      const float4* G4=(const float4*)sG2;
      float4 a0=Z4,a1=Z4,a2=Z4,a3=Z4;
      #pragma unroll 6
      for(int g=0;g<36;g++){
        float4 gv=G4[g*32+f4];
        if(rg8>0) FMA4(a0,sFG[r0*36+g],gv);
        FMA4(a1,sFG[r1*36+g],gv);
        FMA4(a2,sFG[r2*36+g],gv);
        if(rg8==0) FMA4(a3,sFG[24*36+g],gv);
      }
      if(rg8==0) a0=silu4(((const float4*)sGate)[f4]);
      float4* F4=(float4*)sF1;
      F4[r0*32+f4]=a0; F4[r1*32+f4]=a1; F4[r2*32+f4]=a2;
      if(rg8==0) F4[24*32+f4]=a3;
    }
    __syncthreads();
    // out = XN + F1 @ ffn_w2 (+b2 row0)
    {
      int r0=rg, r1=rg+16; bool v1=(r1<25);
      const float4* w4=(const float4*)sW2;
      float4 a0=((const float4*)sXN)[r0*16+c4];
      float4 a1=v1? ((const float4*)sXN)[r1*16+c4] : Z4;
      if(r0==0){ float4 b=((const float4*)sB2)[c4]; a0.x+=b.x;a0.y+=b.y;a0.z+=b.z;a0.w+=b.w; }
      #pragma unroll 8
      for(int f=0;f<128;f++){
        float4 wv=w4[f*16+c4];
        FMA4(a0,sF1[r0*128+f],wv);
        if(v1) FMA4(a1,sF1[r1*128+f],wv);
      }
      float4* op=(float4*)(out+(size_t)n*1600);
      op[r0*16+c4]=a0;
      if(v1) op[r1*16+c4]=a1;
    }
    __syncthreads();
  }
}

extern "C" void kernel_launch(void* const* d_in, const int* in_sizes, int n_in,
                              void* d_out, int out_size) {
  const float* x    = (const float*)d_in[0];
  const int*   ei   = (const int*)d_in[1];
  const int*   zn   = (const int*)d_in[2];
  const float* ed   = (const float*)d_in[3];
  const float* wigr = (const float*)d_in[4];
  const float* stab = (const float*)d_in[5];
  const float* ttab = (const float*)d_in[6];
  const float* rw1  = (const float*)d_in[7];
  const float* rb1  = (const float*)d_in[8];
  const float* rw2  = (const float*)d_in[9];
  const float* rb2  = (const float*)d_in[10];
  const float* rw3  = (const float*)d_in[11];
  const float* rb3  = (const float*)d_in[12];
  const float* W1   = (const float*)d_in[13];
  const float* W0e  = (const float*)d_in[14];
  const float* adot = (const float*)d_in[15];
  const float* tg   = (const float*)d_in[16];
  const float* fg   = (const float*)d_in[17];
  const float* po   = (const float*)d_in[18];
  const float* gm1  = (const float*)d_in[19];
  const float* gm2  = (const float*)d_in[20];
  const float* glw  = (const float*)d_in[21];
  const float* glb  = (const float*)d_in[22];
  const float* fw1  = (const float*)d_in[23];
  const float* fb1  = (const float*)d_in[24];
  const float* fw2  = (const float*)d_in[25];
  const float* fb2  = (const float*)d_in[26];
  float* out = (float*)d_out;

  void *pcnt, *pamax, *pasum;
  cudaGetSymbolAddress(&pcnt,  g_cnt);
  cudaGetSymbolAddress(&pamax, g_amax);
  cudaGetSymbolAddress(&pasum, g_asum);
  cudaMemsetAsync(pcnt,  0, NN*sizeof(int));
  cudaMemsetAsync(pamax, 0, NN*8*sizeof(unsigned));
  cudaMemsetAsync(pasum, 0, NN*8*sizeof(float));

  const int RAD_SMEM  = 52864*4;
  const int EDGE_SMEM = (8192+24576+900+900+128 + 2*9532)*4;   // 215040
  const int NODE_SMEM = (30856 + 2*11144)*4;                   // 212576
  cudaFuncSetAttribute(k_rad,  cudaFuncAttributeMaxDynamicSharedMemorySize, RAD_SMEM);
  cudaFuncSetAttribute(k_edge, cudaFuncAttributeMaxDynamicSharedMemorySize, EDGE_SMEM);
  cudaFuncSetAttribute(k_node, cudaFuncAttributeMaxDynamicSharedMemorySize, NODE_SMEM);

  k_rms1<<<(NN+3)/4, dim3(64,4)>>>(x, gm1);
  k_count<<<(EE+255)/256, 256>>>(ei);
  k_scan<<<1, 1024>>>();
  k_fill<<<(EE+255)/256, 256>>>(ei);
  k_rad<<<296, 256, RAD_SMEM>>>(ed, ei, zn, stab, ttab, rw1, rb1, rw2, rb2, rw3, rb3);
  k_edge<<<148, 512, EDGE_SMEM>>>(wigr, ei, W1, W0e, adot, tg, fg);
  k_att<<<(EE*8+255)/256, 256>>>(ei);
  k_node<<<148, 512, NODE_SMEM>>>(x, out, po, gm2, glw, glb, fw1, fb1, fw2, fb2, tg, fg);
}

// round 6
// speedup vs baseline: 2.5598x; 1.0622x over previous
#include <cuda_runtime.h>

#define NN 10000
#define EE 50000
#define NC 25

__constant__ int c_lof[NC] = {0,1,1,1,2,2,2,2,2,3,3,3,3,3,3,3,4,4,4,4,4,4,4,4,4};

__device__ float    g_h[(size_t)NN*1600];
__device__ float    g_r[(size_t)EE*640];
__device__ float    g_msg[(size_t)EE*1600];
__device__ float    g_alpha[EE*8];
__device__ int      g_cnt[NN];
__device__ int      g_rp[NN+1];
__device__ int      g_cur[NN];
__device__ int      g_ce[EE];

__device__ __forceinline__ float silu(float x){ return x/(1.f+__expf(-x)); }
__device__ __forceinline__ float4 silu4(float4 v){
  return make_float4(silu(v.x),silu(v.y),silu(v.z),silu(v.w));
}
#define FMA4(a,s,v) { (a).x=fmaf((s),(v).x,(a).x); (a).y=fmaf((s),(v).y,(a).y); \
                      (a).z=fmaf((s),(v).z,(a).z); (a).w=fmaf((s),(v).w,(a).w); }
#define MUL4(a,v)   { (a).x*=(v).x; (a).y*=(v).y; (a).z*=(v).z; (a).w*=(v).w; }
#define Z4 make_float4(0.f,0.f,0.f,0.f)
// per-group named barrier (groups of 256 threads, ids 1/2)
#define GBAR() asm volatile("bar.sync %0, %1;" :: "r"(grp+1), "r"(256) : "memory")

// ---------------- rmsnorm1 ----------------
__global__ void k_rms1(const float* __restrict__ x, const float* __restrict__ gamma){
  int n = blockIdx.x*4 + threadIdx.y;
  if(n >= NN) return;
  int c = threadIdx.x;
  const float* xp = x + (size_t)n*1600 + c;
  float s = 0.f;
  #pragma unroll
  for(int i=0;i<NC;i++){ float v = xp[i*64]; s += v*v; }
  float gm = rsqrtf(s*(1.f/25.f) + 1e-6f) * gamma[c];
  float* hp = g_h + (size_t)n*1600 + c;
  #pragma unroll
  for(int i=0;i<NC;i++) hp[i*64] = xp[i*64]*gm;
}

// ---------------- CSR build ----------------
__global__ void k_count(const int* __restrict__ ei){
  int e = blockIdx.x*256 + threadIdx.x;
  if(e < EE) atomicAdd(&g_cnt[ei[EE+e]], 1);
}
__global__ void k_scan(){
  __shared__ int ps[1024];
  int t = threadIdx.x;
  int v[10]; int s = 0;
  #pragma unroll
  for(int m=0;m<10;m++){ int i=t*10+m; int c=(i<NN)? g_cnt[i]:0; v[m]=s; s+=c; }
  ps[t]=s; __syncthreads();
  for(int off=1; off<1024; off<<=1){
    int val=(t>=off)? ps[t-off]:0; __syncthreads();
    ps[t]+=val; __syncthreads();
  }
  int excl=(t>0)? ps[t-1]:0;
  #pragma unroll
  for(int m=0;m<10;m++){
    int i=t*10+m;
    if(i<NN){ int o=excl+v[m]; g_rp[i]=o; g_cur[i]=o; }
  }
  if(t==0) g_rp[NN]=EE;
}
__global__ void k_fill(const int* __restrict__ ei){
  int e = blockIdx.x*256 + threadIdx.x;
  if(e < EE) g_ce[atomicAdd(&g_cur[ei[EE+e]],1)] = e;
}

// ---------------- radial MLP ----------------
__global__ __launch_bounds__(256,1)
void k_rad(const float* __restrict__ ed, const int* __restrict__ ei,
           const int* __restrict__ zn,
           const float* __restrict__ st, const float* __restrict__ tt,
           const float* __restrict__ w1, const float* __restrict__ b1,
           const float* __restrict__ w2, const float* __restrict__ b2,
           const float* __restrict__ w3, const float* __restrict__ b3)
{
  extern __shared__ float sm[];
  float* sw1=sm; float* sw2=sw1+6144; float* sw3=sw2+4096;
  float* sb1=sw3+40960; float* sb2=sb1+64; float* sb3=sb2+64;
  float* ef=sb3+640; float* h1=ef+384; float* h2=h1+256;
  int tid=threadIdx.x;
  for(int i=tid;i<6144;i+=256)  sw1[i]=w1[i];
  for(int i=tid;i<4096;i+=256)  sw2[i]=w2[i];
  for(int i=tid;i<40960;i+=256) sw3[i]=w3[i];
  if(tid<64){ sb1[tid]=b1[tid]; sb2[tid]=b2[tid]; }
  for(int i=tid;i<640;i+=256)   sb3[i]=b3[i];
  __syncthreads();

  int grp=tid>>6, t=tid&63;
  int q=grp;
  int nm=(q<2)?3:2;
  int m0=q, m1=q+4, m2=q+8;

  int iters=(EE+(int)gridDim.x*4-1)/((int)gridDim.x*4);
  for(int it=0; it<iters; it++){
    int e0=(it*(int)gridDim.x+(int)blockIdx.x)*4;
    int e=e0+grp;
    bool valid=(e<EE);
    if(t<32){
      if(valid){
        int src=ei[e], dst=ei[EE+e];
        ef[grp*96+t]   =ed[(size_t)e*32+t];
        ef[grp*96+32+t]=st[zn[src]*32+t];
        ef[grp*96+64+t]=tt[zn[dst]*32+t];
      } else {
        ef[grp*96+t]=0.f; ef[grp*96+32+t]=0.f; ef[grp*96+64+t]=0.f;
      }
    }
    __syncthreads();
    {
      float acc=sb1[t];
      const float4* ef4=(const float4*)(ef+grp*96);
      #pragma unroll
      for(int k4=0;k4<24;k4++){
        float4 v=ef4[k4];
        acc=fmaf(v.x,sw1[(k4*4+0)*64+t],acc);
        acc=fmaf(v.y,sw1[(k4*4+1)*64+t],acc);
        acc=fmaf(v.z,sw1[(k4*4+2)*64+t],acc);
        acc=fmaf(v.w,sw1[(k4*4+3)*64+t],acc);
      }
      h1[grp*64+t]=silu(acc);
    }
    __syncthreads();
    {
      float acc=sb2[t];
      const float4* h14=(const float4*)(h1+grp*64);
      #pragma unroll
      for(int k4=0;k4<16;k4++){
        float4 v=h14[k4];
        acc=fmaf(v.x,sw2[(k4*4+0)*64+t],acc);
        acc=fmaf(v.y,sw2[(k4*4+1)*64+t],acc);
        acc=fmaf(v.z,sw2[(k4*4+2)*64+t],acc);
        acc=fmaf(v.w,sw2[(k4*4+3)*64+t],acc);
      }
      h2[grp*64+t]=silu(acc);
    }
    __syncthreads();
    {
      float a0[4], a1[4], a2[4];
      #pragma unroll
      for(int ee=0;ee<4;ee++){ a0[ee]=sb3[t+64*m0]; a1[ee]=sb3[t+64*m1]; a2[ee]=(nm==3)?sb3[t+64*m2]:0.f; }
      for(int k=0;k<64;k++){
        float hh0=h2[k], hh1=h2[64+k], hh2v=h2[128+k], hh3=h2[192+k];
        float wA=sw3[k*640+t+64*m0];
        float wB=sw3[k*640+t+64*m1];
        a0[0]=fmaf(wA,hh0,a0[0]); a0[1]=fmaf(wA,hh1,a0[1]); a0[2]=fmaf(wA,hh2v,a0[2]); a0[3]=fmaf(wA,hh3,a0[3]);
        a1[0]=fmaf(wB,hh0,a1[0]); a1[1]=fmaf(wB,hh1,a1[1]); a1[2]=fmaf(wB,hh2v,a1[2]); a1[3]=fmaf(wB,hh3,a1[3]);
        if(nm==3){
          float wC=sw3[k*640+t+64*m2];
          a2[0]=fmaf(wC,hh0,a2[0]); a2[1]=fmaf(wC,hh1,a2[1]); a2[2]=fmaf(wC,hh2v,a2[2]); a2[3]=fmaf(wC,hh3,a2[3]);
        }
      }
      #pragma unroll
      for(int ee=0;ee<4;ee++){
        int eo=e0+ee;
        if(eo<EE){
          g_r[(size_t)eo*640+t+64*m0]=a0[ee];
          g_r[(size_t)eo*640+t+64*m1]=a1[ee];
          if(nm==3) g_r[(size_t)eo*640+t+64*m2]=a2[ee];
        }
      }
    }
    __syncthreads();
  }
}

// ---------------- per-edge kernel: 2 edges in flight, per-group barriers ----------------
__global__ __launch_bounds__(512,1)
void k_edge(const float* __restrict__ wigner, const int* __restrict__ ei,
            const float* __restrict__ W1, const float* __restrict__ W0,
            const float* __restrict__ adot, const float* __restrict__ tg,
            const float* __restrict__ fg)
{
  extern __shared__ float sm[];
  float* sW1 = sm;          // 8192
  float* sW0 = sW1+8192;    // 24576 transposed
  float* sTG = sW0+24576;   // 900
  float* sFG = sTG+900;     // 900
  float* sAD = sFG+900;     // 128
  float* pe  = sAD+128;     // 2 * 9532
  int tid=threadIdx.x;
  for(int i=tid;i<8192;i+=512) sW1[i]=W1[i];
  for(int i=tid;i<24576;i+=512){ int o=i>>7,c=i&127; sW0[i]=W0[c*192+o]; }
  for(int i=tid;i<900;i+=512){ sTG[i]=tg[i]; sFG[i]=fg[i]; }
  if(tid<128) sAD[tid]=adot[tid];
  __syncthreads();

  int grp = tid>>8, t = tid&255;
  float* swig  = pe + grp*9532;  // 700
  float* scat  = swig+700;       // 3200 (reused as sgrid)
  float* srr   = scat+3200;      // 640
  float* sxe   = srr+640;        // 3200
  float* sextra= sxe+3200;       // 192
  float* smsg  = sextra+192;     // 1600 (reused as smact)
  float* sgrid = scat;
  float* smact = smsg;

  int c4=t&31, rg8=t>>5;
  int h4=t&15, rg16=t>>4;

  for(int eb=blockIdx.x*2; eb<EE; eb+=gridDim.x*2){
    int e = eb + grp;
    int src=ei[e], dst=ei[EE+e]; (void)dst;
    const float* wp=wigner+(size_t)e*625;
    for(int i=t;i<625;i+=256) swig[(i/25)*28+(i%25)]=wp[i];
    const float4* hs=(const float4*)(g_h+(size_t)src*1600);
    const float4* hd=(const float4*)(g_h+(size_t)dst*1600);
    float4* cat4=(float4*)scat;
    for(int i=t;i<800;i+=256){ int j=i>>5,qq=i&31; cat4[i]=(qq<16)?hs[j*16+qq]:hd[j*16+qq-16]; }
    const float4* rp4=(const float4*)(g_r+(size_t)e*640);
    float4* srr4=(float4*)srr;
    for(int i=t;i<160;i+=256) srr4[i]=rp4[i];
    GBAR();

    // xe = (wig @ cat) * r[EXPAND]
    {
      const float4* catp=(const float4*)scat;
      const float4* r4=(const float4*)srr;
      float4* xe4=(float4*)sxe;
      int r0=rg8, r1=rg8+8, r2=rg8+16;
      float4 a0=Z4,a1=Z4,a2=Z4,a3=Z4;
      #pragma unroll
      for(int j4=0;j4<6;j4++){
        float4 w0=*(const float4*)&swig[r0*28+j4*4];
        float4 w1v=*(const float4*)&swig[r1*28+j4*4];
        float4 w2v=*(const float4*)&swig[r2*28+j4*4];
        float4 w3v=*(const float4*)&swig[24*28+j4*4];
        #pragma unroll
        for(int tt2=0;tt2<4;tt2++){
          float4 cv=catp[(j4*4+tt2)*32+c4];
          FMA4(a0,((const float*)&w0)[tt2],cv);
          FMA4(a1,((const float*)&w1v)[tt2],cv);
          FMA4(a2,((const float*)&w2v)[tt2],cv);
          if(rg8==0) FMA4(a3,((const float*)&w3v)[tt2],cv);
        }
      }
      { float4 cv=catp[24*32+c4];
        FMA4(a0,swig[r0*28+24],cv); FMA4(a1,swig[r1*28+24],cv); FMA4(a2,swig[r2*28+24],cv);
        if(rg8==0) FMA4(a3,swig[24*28+24],cv);
      }
      float4 rv;
      rv=r4[c_lof[r0]*32+c4]; MUL4(a0,rv); xe4[r0*32+c4]=a0;
      rv=r4[c_lof[r1]*32+c4]; MUL4(a1,rv); xe4[r1*32+c4]=a1;
      rv=r4[c_lof[r2]*32+c4]; MUL4(a2,rv); xe4[r2*32+c4]=a2;
      if(rg8==0){ rv=r4[4*32+c4]; MUL4(a3,rv); xe4[24*32+c4]=a3; }
    }
    GBAR();

    // extra = xe[0,:] @ W0_extra
    if(t<192){
      const float4* x0=(const float4*)sxe;
      const float4* w=(const float4*)(sW0+t*128);
      float4 acc=Z4;
      #pragma unroll 8
      for(int k=0;k<32;k++){ float4 xv=x0[k], wv=w[k];
        acc.x=fmaf(xv.x,wv.x,acc.x); acc.y=fmaf(xv.y,wv.y,acc.y);
        acc.z=fmaf(xv.z,wv.z,acc.z); acc.w=fmaf(xv.w,wv.w,acc.w); }
      sextra[t]=acc.x+acc.y+acc.z+acc.w;
    }
    GBAR();

    // alpha (no atomics — segment stats computed in k_node)
    if(t<8){
      float acc=0.f;
      #pragma unroll
      for(int a=0;a<16;a++){ float v=sextra[t*16+a]; acc=fmaf(silu(v),sAD[t*16+a],acc); }
      g_alpha[e*8+t]=acc;
    }
    // msg = xe @ W1
    {
      int r0=rg16, r1=rg16+16; bool v1=(r1<25);
      const float4* x0=(const float4*)(sxe+r0*128);
      const float4* x1=(const float4*)(sxe+(v1?r1:0)*128);
      const float4* w4=(const float4*)sW1;
      float4 a0=Z4,a1=Z4;
      #pragma unroll 8
      for(int ci=0;ci<32;ci++){
        float4 xv0=x0[ci], xv1=x1[ci];
        #pragma unroll
        for(int tt2=0;tt2<4;tt2++){
          float4 wv=w4[(ci*4+tt2)*16+h4];
          FMA4(a0,((const float*)&xv0)[tt2],wv);
          FMA4(a1,((const float*)&xv1)[tt2],wv);
        }
      }
      ((float4*)smsg)[r0*16+h4]=a0;
      if(v1) ((float4*)smsg)[r1*16+h4]=a1;
    }
    GBAR();

    // grid = silu(to_grid @ msg)
    {
      int g0=rg16, g1=rg16+16, g2=rg16+32; bool v2=(g2<36);
      const float4* m4=(const float4*)smsg;
      float4* gr4=(float4*)sgrid;
      float4 a0=Z4,a1=Z4,a2=Z4;
      #pragma unroll
      for(int i=0;i<25;i++){
        float4 mv=m4[i*16+h4];
        FMA4(a0,sTG[g0*25+i],mv);
        FMA4(a1,sTG[g1*25+i],mv);
        if(v2) FMA4(a2,sTG[g2*25+i],mv);
      }
      gr4[g0*16+h4]=silu4(a0);
      gr4[g1*16+h4]=silu4(a1);
      if(v2) gr4[g2*16+h4]=silu4(a2);
    }
    GBAR();

    // mact = [silu(gate); from_grid @ grid]
    {
      int r0=rg16, r1=rg16+16; bool v1=(r1<25);
      const float4* gr4=(const float4*)sgrid;
      float4 a0=Z4,a1=Z4;
      #pragma unroll 6
      for(int g=0;g<36;g++){
        float4 gv=gr4[g*16+h4];
        if(rg16>0) FMA4(a0,sFG[r0*36+g],gv);
        if(v1)     FMA4(a1,sFG[r1*36+g],gv);
      }
      if(rg16==0) a0=silu4(((const float4*)(sextra+128))[h4]);
      ((float4*)smact)[r0*16+h4]=a0;
      if(v1) ((float4*)smact)[r1*16+h4]=a1;
    }
    GBAR();

    // rotated = wig^T @ mact -> global
    {
      int r0=rg16, r1=rg16+16; bool v1=(r1<25);
      const float4* m4=(const float4*)smact;
      float4 a0=Z4,a1=Z4;
      #pragma unroll
      for(int j=0;j<25;j++){
        float4 mv=m4[j*16+h4];
        FMA4(a0,swig[j*28+r0],mv);
        if(v1) FMA4(a1,swig[j*28+r1],mv);
      }
      float4* op=(float4*)(g_msg+(size_t)e*1600);
      op[r0*16+h4]=a0;
      if(v1) op[r1*16+h4]=a1;
    }
    GBAR();
  }
}

// ---------------- node: fused softmax + gather + proj + rmsnorm2 + FFN ----------------
__global__ __launch_bounds__(512,1)
void k_node(const float* __restrict__ x, float* __restrict__ out,
            const float* __restrict__ po, const float* __restrict__ g2w,
            const float* __restrict__ glw, const float* __restrict__ glb,
            const float* __restrict__ fw1, const float* __restrict__ fb1,
            const float* __restrict__ fw2, const float* __restrict__ fb2,
            const float* __restrict__ tg, const float* __restrict__ fg)
{
  extern __shared__ float sm[];
  float* sPO  = sm;           // 4096
  float* sGL  = sPO+4096;     // 8192
  float* sW1f = sGL+8192;     // 8192
  float* sW2  = sW1f+8192;    // 8192
  float* sTG  = sW2+8192;     // 900
  float* sFG  = sTG+900;      // 900
  float* sGLB = sFG+900;      // 128
  float* sB1  = sGLB+128;     // 128
  float* sB2  = sB1+128;      // 64
  float* sGam = sB2+64;       // 64
  float* pn   = sGam+64;      // 2 * 11152
  int tid=threadIdx.x;
  for(int i=tid;i<4096;i+=512) sPO[i]=po[i];
  for(int i=tid;i<8192;i+=512){ sGL[i]=glw[i]; sW1f[i]=fw1[i]; sW2[i]=fw2[i]; }
  for(int i=tid;i<900;i+=512){ sTG[i]=tg[i]; sFG[i]=fg[i]; }
  if(tid<128){ sGLB[tid]=glb[tid]; sB1[tid]=fb1[tid]; }
  if(tid<64){ sB2[tid]=fb2[tid]; sGam[tid]=g2w[tid]; }
  __syncthreads();

  int grp=tid>>8, t=tid&255;
  float* sWinv= pn + grp*11152; // 8
  float* sMax = sWinv+8;        // 8
  float* sXN  = sMax+8;         // 1600
  float* sH   = sXN+1600;       // 1600
  float* sGate= sH+1600;        // 128
  float* sF1  = sGate+128;      // 3200
  float* sG2  = sF1+3200;       // 4608 (sA aliased)
  float* sA   = sG2;

  int c4=t&15, rg=t>>4;
  int f4=t&31, rg8=t>>5;

  for(int nb=blockIdx.x*2; nb<NN; nb+=gridDim.x*2){
    int n = nb + grp;
    int beg=g_rp[n], end=g_rp[n+1];
    float4* sA4=(float4*)sA;
    for(int i=t;i<400;i+=256) sA4[i]=Z4;
    // softmax stats over this node's edges (head t<8)
    if(t<8){
      float m=-3.0e38f;
      for(int k=beg;k<end;k++){ float a=g_alpha[g_ce[k]*8+t]; m=fmaxf(m,a); }
      float s=0.f;
      for(int k=beg;k<end;k++){ float a=g_alpha[g_ce[k]*8+t]; s+=__expf(a-m); }
      sMax[t]=m;
      sWinv[t]=1.f/(s+1e-8f);
    }
    GBAR();
    for(int k=beg;k<end;k++){
      int e=g_ce[k];
      const float4* mp=(const float4*)(g_msg+(size_t)e*1600);
      for(int i=t;i<400;i+=256){
        int h=(i&15)>>1;
        float w=__expf(g_alpha[e*8+h]-sMax[h])*sWinv[h];
        float4 v=mp[i];
        float4 a=sA4[i];
        FMA4(a,w,v);
        sA4[i]=a;
      }
    }
    GBAR();

    // XN = x + agg @ proj_out
    {
      int r0=rg, r1=rg+16; bool v1=(r1<25);
      const float4* x4=(const float4*)(x+(size_t)n*1600);
      const float4* p4=(const float4*)sPO;
      float4 a0=x4[r0*16+c4];
      float4 a1=v1? x4[r1*16+c4] : Z4;
      #pragma unroll 8
      for(int k=0;k<64;k++){
        float4 wv=p4[k*16+c4];
        FMA4(a0,sA[r0*64+k],wv);
        if(v1) FMA4(a1,sA[r1*64+k],wv);
      }
      ((float4*)sXN)[r0*16+c4]=a0;
      if(v1) ((float4*)sXN)[r1*16+c4]=a1;
    }
    GBAR();
    if(t<64){
      float s=0.f;
      #pragma unroll
      for(int i=0;i<NC;i++){ float v=sXN[i*64+t]; s=fmaf(v,v,s); }
      sGate[t]=rsqrtf(s*(1.f/25.f)+1e-6f)*sGam[t];  // rinv temp
    }
    GBAR();
    {
      float4* sH4=(float4*)sH;
      const float4* xn4=(const float4*)sXN;
      const float4* rv4=(const float4*)sGate;
      for(int i=t;i<400;i+=256){ float4 v=xn4[i], r=rv4[i&15]; MUL4(v,r); sH4[i]=v; }
    }
    GBAR();
    float gacc=0.f;
    if(t<128){
      gacc=sGLB[t];
      #pragma unroll 8
      for(int c=0;c<64;c++) gacc=fmaf(sH[c],sGL[c*128+t],gacc);
    }
    GBAR();
    if(t<128) sGate[t]=gacc;
    // F1 = h @ ffn_w1 (+b1 row0)
    {
      int r0=rg8, r1=rg8+8, r2=rg8+16;
      const float4* w4=(const float4*)sW1f;
      float4 a0=Z4,a1=Z4,a2=Z4,a3=Z4;
      #pragma unroll 8
      for(int c=0;c<64;c++){
        float4 wv=w4[c*32+f4];
        FMA4(a0,sH[r0*64+c],wv);
        FMA4(a1,sH[r1*64+c],wv);
        FMA4(a2,sH[r2*64+c],wv);
        if(rg8==0) FMA4(a3,sH[24*64+c],wv);
      }
      if(rg8==0){ float4 b=((const float4*)sB1)[f4]; a0.x+=b.x;a0.y+=b.y;a0.z+=b.z;a0.w+=b.w; }
      float4* F4=(float4*)sF1;
      F4[r0*32+f4]=a0; F4[r1*32+f4]=a1; F4[r2*32+f4]=a2;
      if(rg8==0) F4[24*32+f4]=a3;
    }
    GBAR();
    // G2 = silu(to_grid @ F1)
    {
      int g0=rg8, g1=rg8+8, g2=rg8+16, g3=rg8+24, g4v=rg8+32; bool v4=(g4v<36);
      const float4* F4=(const float4*)sF1;
      float4* G4=(float4*)sG2;
      float4 a0=Z4,a1=Z4,a2=Z4,a3=Z4,a4=Z4;
      #pragma unroll
      for(int i=0;i<25;i++){
        float4 fv=F4[i*32+f4];
        FMA4(a0,sTG[g0*25+i],fv);
        FMA4(a1,sTG[g1*25+i],fv);
        FMA4(a2,sTG[g2*25+i],fv);
        FMA4(a3,sTG[g3*25+i],fv);
        if(v4) FMA4(a4,sTG[g4v*25+i],fv);
      }
      G4[g0*32+f4]=silu4(a0); G4[g1*32+f4]=silu4(a1);
      G4[g2*32+f4]=silu4(a2); G4[g3*32+f4]=silu4(a3);
      if(v4) G4[g4v*32+f4]=silu4(a4);
    }
    GBAR();
    // F1 := [silu(gate); from_grid @ G2]
    {
      int r0=rg8, r1=rg8+8, r2=rg8+16;
      const float4* G4=(const float4*)sG2;
      float4 a0=Z4,a1=Z4,a2=Z4,a3=Z4;
      #pragma unroll 6
      for(int g=0;g<36;g++){
        float4 gv=G4[g*32+f4];
        if(rg8>0) FMA4(a0,sFG[r0*36+g],gv);
        FMA4(a1,sFG[r1*36+g],gv);
        FMA4(a2,sFG[r2*36+g],gv);
        if(rg8==0) FMA4(a3,sFG[24*36+g],gv);
      }
      if(rg8==0) a0=silu4(((const float4*)sGate)[f4]);
      float4* F4=(float4*)sF1;
      F4[r0*32+f4]=a0; F4[r1*32+f4]=a1; F4[r2*32+f4]=a2;
      if(rg8==0) F4[24*32+f4]=a3;
    }
    GBAR();
    // out = XN + F1 @ ffn_w2 (+b2 row0)
    {
      int r0=rg, r1=rg+16; bool v1=(r1<25);
      const float4* w4=(const float4*)sW2;
      float4 a0=((const float4*)sXN)[r0*16+c4];
      float4 a1=v1? ((const float4*)sXN)[r1*16+c4] : Z4;
      if(r0==0){ float4 b=((const float4*)sB2)[c4]; a0.x+=b.x;a0.y+=b.y;a0.z+=b.z;a0.w+=b.w; }
      #pragma unroll 8
      for(int f=0;f<128;f++){
        float4 wv=w4[f*16+c4];
        FMA4(a0,sF1[r0*128+f],wv);
        if(v1) FMA4(a1,sF1[r1*128+f],wv);
      }
      float4* op=(float4*)(out+(size_t)n*1600);
      op[r0*16+c4]=a0;
      if(v1) op[r1*16+c4]=a1;
    }
    GBAR();
  }
}

extern "C" void kernel_launch(void* const* d_in, const int* in_sizes, int n_in,
                              void* d_out, int out_size) {
  const float* x    = (const float*)d_in[0];
  const int*   ei   = (const int*)d_in[1];
  const int*   zn   = (const int*)d_in[2];
  const float* ed   = (const float*)d_in[3];
  const float* wigr = (const float*)d_in[4];
  const float* stab = (const float*)d_in[5];
  const float* ttab = (const float*)d_in[6];
  const float* rw1  = (const float*)d_in[7];
  const float* rb1  = (const float*)d_in[8];
  const float* rw2  = (const float*)d_in[9];
  const float* rb2  = (const float*)d_in[10];
  const float* rw3  = (const float*)d_in[11];
  const float* rb3  = (const float*)d_in[12];
  const float* W1   = (const float*)d_in[13];
  const float* W0e  = (const float*)d_in[14];
  const float* adot = (const float*)d_in[15];
  const float* tg   = (const float*)d_in[16];
  const float* fg   = (const float*)d_in[17];
  const float* po   = (const float*)d_in[18];
  const float* gm1  = (const float*)d_in[19];
  const float* gm2  = (const float*)d_in[20];
  const float* glw  = (const float*)d_in[21];
  const float* glb  = (const float*)d_in[22];
  const float* fw1  = (const float*)d_in[23];
  const float* fb1  = (const float*)d_in[24];
  const float* fw2  = (const float*)d_in[25];
  const float* fb2  = (const float*)d_in[26];
  float* out = (float*)d_out;

  void *pcnt;
  cudaGetSymbolAddress(&pcnt, g_cnt);
  cudaMemsetAsync(pcnt, 0, NN*sizeof(int));

  const int RAD_SMEM  = 52864*4;
  const int EDGE_SMEM = (8192+24576+900+900+128 + 2*9532)*4;   // 215040
  const int NODE_SMEM = (30856 + 2*11152)*4;                   // 212640
  cudaFuncSetAttribute(k_rad,  cudaFuncAttributeMaxDynamicSharedMemorySize, RAD_SMEM);
  cudaFuncSetAttribute(k_edge, cudaFuncAttributeMaxDynamicSharedMemorySize, EDGE_SMEM);
  cudaFuncSetAttribute(k_node, cudaFuncAttributeMaxDynamicSharedMemorySize, NODE_SMEM);

  k_rms1<<<(NN+3)/4, dim3(64,4)>>>(x, gm1);
  k_count<<<(EE+255)/256, 256>>>(ei);
  k_scan<<<1, 1024>>>();
  k_fill<<<(EE+255)/256, 256>>>(ei);
  k_rad<<<296, 256, RAD_SMEM>>>(ed, ei, zn, stab, ttab, rw1, rb1, rw2, rb2, rw3, rb3);
  k_edge<<<148, 512, EDGE_SMEM>>>(wigr, ei, W1, W0e, adot, tg, fg);
  k_node<<<148, 512, NODE_SMEM>>>(x, out, po, gm2, glw, glb, fw1, fb1, fw2, fb2, tg, fg);
}

// round 8
// speedup vs baseline: 2.6780x; 1.0462x over previous
#include <cuda_runtime.h>

#define NN 10000
#define EE 50000
#define NC 25
#define EPG 10232
#define NPG 12224

__constant__ int c_lof[NC] = {0,1,1,1,2,2,2,2,2,3,3,3,3,3,3,3,4,4,4,4,4,4,4,4,4};

__device__ float    g_h[(size_t)NN*1600];
__device__ float    g_r[(size_t)EE*640];
__device__ float    g_msg[(size_t)EE*1600];
__device__ float    g_alpha[EE*8];
__device__ int      g_cnt[NN];
__device__ int      g_rp[NN+1];
__device__ int      g_cur[NN];
__device__ int      g_ce[EE];

__device__ __forceinline__ float silu(float x){ return x/(1.f+__expf(-x)); }
__device__ __forceinline__ float4 silu4(float4 v){
  return make_float4(silu(v.x),silu(v.y),silu(v.z),silu(v.w));
}
#define FMA4(a,s,v) { (a).x=fmaf((s),(v).x,(a).x); (a).y=fmaf((s),(v).y,(a).y); \
                      (a).z=fmaf((s),(v).z,(a).z); (a).w=fmaf((s),(v).w,(a).w); }
#define MUL4(a,v)   { (a).x*=(v).x; (a).y*=(v).y; (a).z*=(v).z; (a).w*=(v).w; }
#define Z4 make_float4(0.f,0.f,0.f,0.f)
#define GBAR() asm volatile("bar.sync %0, %1;" :: "r"(grp+1), "r"(256) : "memory")

// ---------------- rmsnorm1 ----------------
__global__ void k_rms1(const float* __restrict__ x, const float* __restrict__ gamma){
  int n = blockIdx.x*4 + threadIdx.y;
  if(n >= NN) return;
  int c = threadIdx.x;
  const float* xp = x + (size_t)n*1600 + c;
  float s = 0.f;
  #pragma unroll
  for(int i=0;i<NC;i++){ float v = xp[i*64]; s += v*v; }
  float gm = rsqrtf(s*(1.f/25.f) + 1e-6f) * gamma[c];
  float* hp = g_h + (size_t)n*1600 + c;
  #pragma unroll
  for(int i=0;i<NC;i++) hp[i*64] = xp[i*64]*gm;
}

// ---------------- CSR build ----------------
__global__ void k_count(const int* __restrict__ ei){
  int e = blockIdx.x*256 + threadIdx.x;
  if(e < EE) atomicAdd(&g_cnt[ei[EE+e]], 1);
}
__global__ void k_scan(){
  __shared__ int ps[1024];
  int t = threadIdx.x;
  int v[10]; int s = 0;
  #pragma unroll
  for(int m=0;m<10;m++){ int i=t*10+m; int c=(i<NN)? g_cnt[i]:0; v[m]=s; s+=c; }
  ps[t]=s; __syncthreads();
  for(int off=1; off<1024; off<<=1){
    int val=(t>=off)? ps[t-off]:0; __syncthreads();
    ps[t]+=val; __syncthreads();
  }
  int excl=(t>0)? ps[t-1]:0;
  #pragma unroll
  for(int m=0;m<10;m++){
    int i=t*10+m;
    if(i<NN){ int o=excl+v[m]; g_rp[i]=o; g_cur[i]=o; }
  }
  if(t==0) g_rp[NN]=EE;
}
__global__ void k_fill(const int* __restrict__ ei){
  int e = blockIdx.x*256 + threadIdx.x;
  if(e < EE) g_ce[atomicAdd(&g_cur[ei[EE+e]],1)] = e;
}

// ---------------- radial MLP ----------------
__global__ __launch_bounds__(256,1)
void k_rad(const float* __restrict__ ed, const int* __restrict__ ei,
           const int* __restrict__ zn,
           const float* __restrict__ st, const float* __restrict__ tt,
           const float* __restrict__ w1, const float* __restrict__ b1,
           const float* __restrict__ w2, const float* __restrict__ b2,
           const float* __restrict__ w3, const float* __restrict__ b3)
{
  extern __shared__ float sm[];
  float* sw1=sm; float* sw2=sw1+6144; float* sw3=sw2+4096;
  float* sb1=sw3+40960; float* sb2=sb1+64; float* sb3=sb2+64;
  float* ef=sb3+640; float* h1=ef+384; float* h2=h1+256;
  int tid=threadIdx.x;
  for(int i=tid;i<6144;i+=256)  sw1[i]=w1[i];
  for(int i=tid;i<4096;i+=256)  sw2[i]=w2[i];
  for(int i=tid;i<40960;i+=256) sw3[i]=w3[i];
  if(tid<64){ sb1[tid]=b1[tid]; sb2[tid]=b2[tid]; }
  for(int i=tid;i<640;i+=256)   sb3[i]=b3[i];
  __syncthreads();

  int grp=tid>>6, t=tid&63;
  int q=grp;
  int nm=(q<2)?3:2;
  int m0=q, m1=q+4, m2=q+8;

  int iters=(EE+(int)gridDim.x*4-1)/((int)gridDim.x*4);
  for(int it=0; it<iters; it++){
    int e0=(it*(int)gridDim.x+(int)blockIdx.x)*4;
    int e=e0+grp;
    bool valid=(e<EE);
    if(t<32){
      if(valid){
        int src=ei[e], dst=ei[EE+e];
        ef[grp*96+t]   =ed[(size_t)e*32+t];
        ef[grp*96+32+t]=st[zn[src]*32+t];
        ef[grp*96+64+t]=tt[zn[dst]*32+t];
      } else {
        ef[grp*96+t]=0.f; ef[grp*96+32+t]=0.f; ef[grp*96+64+t]=0.f;
      }
    }
    __syncthreads();
    {
      float acc=sb1[t];
      const float4* ef4=(const float4*)(ef+grp*96);
      #pragma unroll
      for(int k4=0;k4<24;k4++){
        float4 v=ef4[k4];
        acc=fmaf(v.x,sw1[(k4*4+0)*64+t],acc);
        acc=fmaf(v.y,sw1[(k4*4+1)*64+t],acc);
        acc=fmaf(v.z,sw1[(k4*4+2)*64+t],acc);
        acc=fmaf(v.w,sw1[(k4*4+3)*64+t],acc);
      }
      h1[grp*64+t]=silu(acc);
    }
    __syncthreads();
    {
      float acc=sb2[t];
      const float4* h14=(const float4*)(h1+grp*64);
      #pragma unroll
      for(int k4=0;k4<16;k4++){
        float4 v=h14[k4];
        acc=fmaf(v.x,sw2[(k4*4+0)*64+t],acc);
        acc=fmaf(v.y,sw2[(k4*4+1)*64+t],acc);
        acc=fmaf(v.z,sw2[(k4*4+2)*64+t],acc);
        acc=fmaf(v.w,sw2[(k4*4+3)*64+t],acc);
      }
      h2[grp*64+t]=silu(acc);
    }
    __syncthreads();
    {
      float a0[4], a1[4], a2[4];
      #pragma unroll
      for(int ee=0;ee<4;ee++){ a0[ee]=sb3[t+64*m0]; a1[ee]=sb3[t+64*m1]; a2[ee]=(nm==3)?sb3[t+64*m2]:0.f; }
      for(int k=0;k<64;k++){
        float hh0=h2[k], hh1=h2[64+k], hh2v=h2[128+k], hh3=h2[192+k];
        float wA=sw3[k*640+t+64*m0];
        float wB=sw3[k*640+t+64*m1];
        a0[0]=fmaf(wA,hh0,a0[0]); a0[1]=fmaf(wA,hh1,a0[1]); a0[2]=fmaf(wA,hh2v,a0[2]); a0[3]=fmaf(wA,hh3,a0[3]);
        a1[0]=fmaf(wB,hh0,a1[0]); a1[1]=fmaf(wB,hh1,a1[1]); a1[2]=fmaf(wB,hh2v,a1[2]); a1[3]=fmaf(wB,hh3,a1[3]);
        if(nm==3){
          float wC=sw3[k*640+t+64*m2];
          a2[0]=fmaf(wC,hh0,a2[0]); a2[1]=fmaf(wC,hh1,a2[1]); a2[2]=fmaf(wC,hh2v,a2[2]); a2[3]=fmaf(wC,hh3,a2[3]);
        }
      }
      #pragma unroll
      for(int ee=0;ee<4;ee++){
        int eo=e0+ee;
        if(eo<EE){
          g_r[(size_t)eo*640+t+64*m0]=a0[ee];
          g_r[(size_t)eo*640+t+64*m1]=a1[ee];
          if(nm==3) g_r[(size_t)eo*640+t+64*m2]=a2[ee];
        }
      }
    }
    __syncthreads();
  }
}

// ---------------- per-edge kernel: 2 groups, prefetch pipeline ----------------
__global__ __launch_bounds__(512,1)
void k_edge(const float* __restrict__ wigner, const int* __restrict__ ei,
            const float* __restrict__ W1, const float* __restrict__ W0,
            const float* __restrict__ adot, const float* __restrict__ tg,
            const float* __restrict__ fg)
{
  extern __shared__ float sm[];
  float* sW1 = sm;          // 8192
  float* sW0 = sW1+8192;    // 24576 transposed
  float* sTG = sW0+24576;   // 900
  float* sFG = sTG+900;     // 900
  float* sAD = sFG+900;     // 128
  float* pe  = sAD+128;     // 2 * EPG
  int tid=threadIdx.x;
  for(int i=tid;i<8192;i+=512) sW1[i]=W1[i];
  for(int i=tid;i<24576;i+=512){ int o=i>>7,c=i&127; sW0[i]=W0[c*192+o]; }
  for(int i=tid;i<900;i+=512){ sTG[i]=tg[i]; sFG[i]=fg[i]; }
  if(tid<128) sAD[tid]=adot[tid];
  __syncthreads();

  int grp = tid>>8, t = tid&255;
  float* base  = pe + grp*EPG;
  float* swigA = base;         // 700
  float* swigB = base+700;     // 700
  float* scat  = base+1400;    // 3200
  float* srr   = base+4600;    // 640
  float* sxe   = base+5240;    // 3200 (aliased as sgrid)
  float* sextra= base+8440;    // 192
  float* smsg  = base+8632;    // 1600 (aliased as smact)
  float* sgrid = sxe;
  float* smact = smsg;

  int c4=t&31, rg8=t>>5;
  int h4=t&15, rg16=t>>4;

  int stride = (int)gridDim.x*2;
  int e = (int)blockIdx.x*2 + grp;
  int p = 0;

  // preload first edge
  {
    const float* wp=wigner+(size_t)e*625;
    for(int i=t;i<625;i+=256) swigA[(i/25)*28+(i%25)]=wp[i];
    int src=ei[e], dst=ei[EE+e];
    const float4* hs=(const float4*)(g_h+(size_t)src*1600);
    const float4* hd=(const float4*)(g_h+(size_t)dst*1600);
    float4* cat4=(float4*)scat;
    for(int i=t;i<800;i+=256){ int j=i>>5,qq=i&31; cat4[i]=(qq<16)?hs[j*16+qq]:hd[j*16+qq-16]; }
    const float4* rp4=(const float4*)(g_r+(size_t)e*640);
    float4* srr4=(float4*)srr;
    for(int i=t;i<160;i+=256) srr4[i]=rp4[i];
  }

  for(; e<EE; e+=stride){
    int en = e + stride; if(en >= EE) en = e;   // clamp (wasted prefetch on last iter)
    float* swig  = p? swigB : swigA;
    float* swigN = p? swigA : swigB;
    GBAR();   // prefetched data ready; prev rotate done

    // xe = (wig @ cat) * r[EXPAND]
    {
      const float4* catp=(const float4*)scat;
      const float4* r4=(const float4*)srr;
      float4* xe4=(float4*)sxe;
      int r0=rg8, r1=rg8+8, r2=rg8+16;
      float4 a0=Z4,a1=Z4,a2=Z4,a3=Z4;
      #pragma unroll
      for(int j4=0;j4<6;j4++){
        float4 w0=*(const float4*)&swig[r0*28+j4*4];
        float4 w1v=*(const float4*)&swig[r1*28+j4*4];
        float4 w2v=*(const float4*)&swig[r2*28+j4*4];
        float4 w3v=*(const float4*)&swig[24*28+j4*4];
        #pragma unroll
        for(int tt2=0;tt2<4;tt2++){
          float4 cv=catp[(j4*4+tt2)*32+c4];
          FMA4(a0,((const float*)&w0)[tt2],cv);
          FMA4(a1,((const float*)&w1v)[tt2],cv);
          FMA4(a2,((const float*)&w2v)[tt2],cv);
          if(rg8==0) FMA4(a3,((const float*)&w3v)[tt2],cv);
        }
      }
      { float4 cv=catp[24*32+c4];
        FMA4(a0,swig[r0*28+24],cv); FMA4(a1,swig[r1*28+24],cv); FMA4(a2,swig[r2*28+24],cv);
        if(rg8==0) FMA4(a3,swig[24*28+24],cv);
      }
      float4 rv;
      rv=r4[c_lof[r0]*32+c4]; MUL4(a0,rv); xe4[r0*32+c4]=a0;
      rv=r4[c_lof[r1]*32+c4]; MUL4(a1,rv); xe4[r1*32+c4]=a1;
      rv=r4[c_lof[r2]*32+c4]; MUL4(a2,rv); xe4[r2*32+c4]=a2;
      if(rg8==0){ rv=r4[4*32+c4]; MUL4(a3,rv); xe4[24*32+c4]=a3; }
    }
    GBAR();  // scat/srr now dead; sxe ready

    // prefetch next edge (wigner -> swigN, cat -> scat, r -> srr)
    {
      const float* wp=wigner+(size_t)en*625;
      for(int i=t;i<625;i+=256) swigN[(i/25)*28+(i%25)]=wp[i];
      int nsrc=ei[en], ndst=ei[EE+en];
      const float4* hs=(const float4*)(g_h+(size_t)nsrc*1600);
      const float4* hd=(const float4*)(g_h+(size_t)ndst*1600);
      float4* cat4=(float4*)scat;
      for(int i=t;i<800;i+=256){ int j=i>>5,qq=i&31; cat4[i]=(qq<16)?hs[j*16+qq]:hd[j*16+qq-16]; }
      const float4* rp4=(const float4*)(g_r+(size_t)en*640);
      float4* srr4=(float4*)srr;
      for(int i=t;i<160;i+=256) srr4[i]=rp4[i];
    }

    // msg = xe @ W1  (+ extra by t<192)
    {
      int r0=rg16, r1=rg16+16; bool v1=(r1<25);
      const float4* x0=(const float4*)(sxe+r0*128);
      const float4* x1=(const float4*)(sxe+(v1?r1:0)*128);
      const float4* w4=(const float4*)sW1;
      float4 a0=Z4,a1=Z4;
      #pragma unroll 8
      for(int ci=0;ci<32;ci++){
        float4 xv0=x0[ci], xv1=x1[ci];
        #pragma unroll
        for(int tt2=0;tt2<4;tt2++){
          float4 wv=w4[(ci*4+tt2)*16+h4];
          FMA4(a0,((const float*)&xv0)[tt2],wv);
          FMA4(a1,((const float*)&xv1)[tt2],wv);
        }
      }
      ((float4*)smsg)[r0*16+h4]=a0;
      if(v1) ((float4*)smsg)[r1*16+h4]=a1;
    }
    if(t<192){
      const float4* x0=(const float4*)sxe;
      const float4* w=(const float4*)(sW0+t*128);
      float4 acc=Z4;
      #pragma unroll 8
      for(int k=0;k<32;k++){ float4 xv=x0[k], wv=w[k];
        acc.x=fmaf(xv.x,wv.x,acc.x); acc.y=fmaf(xv.y,wv.y,acc.y);
        acc.z=fmaf(xv.z,wv.z,acc.z); acc.w=fmaf(xv.w,wv.w,acc.w); }
      sextra[t]=acc.x+acc.y+acc.z+acc.w;
    }
    GBAR();

    // grid = silu(to_grid @ msg)  (writes sgrid = sxe region)  + alpha by t<8
    if(t<8){
      float acc=0.f;
      #pragma unroll
      for(int a=0;a<16;a++){ float v=sextra[t*16+a]; acc=fmaf(silu(v),sAD[t*16+a],acc); }
      g_alpha[e*8+t]=acc;
    }
    {
      int g0=rg16, g1=rg16+16, g2=rg16+32; bool v2=(g2<36);
      const float4* m4=(const float4*)smsg;
      float4* gr4=(float4*)sgrid;
      float4 a0=Z4,a1=Z4,a2=Z4;
      #pragma unroll
      for(int i=0;i<25;i++){
        float4 mv=m4[i*16+h4];
        FMA4(a0,sTG[g0*25+i],mv);
        FMA4(a1,sTG[g1*25+i],mv);
        if(v2) FMA4(a2,sTG[g2*25+i],mv);
      }
      gr4[g0*16+h4]=silu4(a0);
      gr4[g1*16+h4]=silu4(a1);
      if(v2) gr4[g2*16+h4]=silu4(a2);
    }
    GBAR();

    // mact = [silu(gate); from_grid @ grid]  (writes smact = smsg region)
    {
      int r0=rg16, r1=rg16+16; bool v1=(r1<25);
      const float4* gr4=(const float4*)sgrid;
      float4 a0=Z4,a1=Z4;
      #pragma unroll 6
      for(int g=0;g<36;g++){
        float4 gv=gr4[g*16+h4];
        if(rg16>0) FMA4(a0,sFG[r0*36+g],gv);
        if(v1)     FMA4(a1,sFG[r1*36+g],gv);
      }
      if(rg16==0) a0=silu4(((const float4*)(sextra+128))[h4]);
      ((float4*)smact)[r0*16+h4]=a0;
      if(v1) ((float4*)smact)[r1*16+h4]=a1;
    }
    GBAR();

    // rotated = wig^T @ mact -> global
    {
      int r0=rg16, r1=rg16+16; bool v1=(r1<25);
      const float4* m4=(const float4*)smact;
      float4 a0=Z4,a1=Z4;
      #pragma unroll
      for(int j=0;j<25;j++){
        float4 mv=m4[j*16+h4];
        FMA4(a0,swig[j*28+r0],mv);
        if(v1) FMA4(a1,swig[j*28+r1],mv);
      }
      float4* op=(float4*)(g_msg+(size_t)e*1600);
      op[r0*16+h4]=a0;
      if(v1) op[r1*16+h4]=a1;
    }
    p ^= 1;
  }
}

// ---------------- node: fused softmax + gather + proj + rmsnorm2 + FFN ----------------
__global__ __launch_bounds__(512,1)
void k_node(const float* __restrict__ x, float* __restrict__ out,
            const float* __restrict__ po, const float* __restrict__ g2w,
            const float* __restrict__ glw, const float* __restrict__ glb,
            const float* __restrict__ fw1, const float* __restrict__ fb1,
            const float* __restrict__ fw2, const float* __restrict__ fb2,
            const float* __restrict__ tg, const float* __restrict__ fg)
{
  extern __shared__ float sm[];
  float* sPO  = sm;           // 4096
  float* sGL  = sPO+4096;     // 8192
  float* sW1f = sGL+8192;     // 8192
  float* sW2  = sW1f+8192;    // 8192
  float* sTG  = sW2+8192;     // 900
  float* sFG  = sTG+900;      // 900
  float* sGLB = sFG+900;      // 128
  float* sB1  = sGLB+128;     // 128
  float* sB2  = sB1+128;      // 64
  float* sGam = sB2+64;       // 64
  float* pn   = sGam+64;      // 2 * NPG
  int tid=threadIdx.x;
  for(int i=tid;i<4096;i+=512) sPO[i]=po[i];
  for(int i=tid;i<8192;i+=512){ sGL[i]=glw[i]; sW1f[i]=fw1[i]; sW2[i]=fw2[i]; }
  for(int i=tid;i<900;i+=512){ sTG[i]=tg[i]; sFG[i]=fg[i]; }
  if(tid<128){ sGLB[tid]=glb[tid]; sB1[tid]=fb1[tid]; }
  if(tid<64){ sB2[tid]=fb2[tid]; sGam[tid]=g2w[tid]; }
  __syncthreads();

  int grp=tid>>8, t=tid&255;
  float* base = pn + grp*NPG;
  float* sCE  = base;          // 64 (int via cast)
  float* sAL  = base+64;       // 512
  float* sEW  = base+576;      // 512
  float* sXN  = base+1088;     // 1600
  float* sH   = sXN+1600;      // 1600
  float* sGate= sH+1600;       // 128 ([0..7]=m, [8..15]=s/winv during stats)
  float* sF1  = sGate+128;     // 3200
  float* sG2  = sF1+3200;      // 4608 (sA alias)
  float* sA   = sG2;
  int* sCEi = (int*)sCE;

  int c4=t&15, rg=t>>4;
  int f4=t&31, rg8=t>>5;

  for(int nb=blockIdx.x*2; nb<NN; nb+=gridDim.x*2){
    int n = nb + grp;
    int beg=g_rp[n], end=g_rp[n+1];
    int deg=end-beg;
    float4* sA4=(float4*)sA;
    for(int i=t;i<400;i+=256) sA4[i]=Z4;
    if(t<16) sGate[t] = (t<8)? -3.0e38f : 0.f;
    GBAR();

    // ---- stats: online softmax over chunks of 64 edges ----
    for(int k0=beg; k0<end; k0+=64){
      int kc=min(64,end-k0);
      for(int idx=t; idx<kc; idx+=256) sCEi[idx]=g_ce[k0+idx];
      GBAR();
      for(int idx=t; idx<kc*2; idx+=256){
        int j=idx>>1, q=idx&1;
        ((float4*)sAL)[j*2+q] = ((const float4*)(g_alpha+(size_t)sCEi[j]*8))[q];
      }
      GBAR();
      if(t<8){
        float m=sGate[t], s=sGate[8+t];
        for(int j=0;j<kc;j++){
          float a=sAL[j*8+t];
          if(a>m){ s=s*__expf(m-a)+1.f; m=a; }
          else    s+=__expf(a-m);
        }
        sGate[t]=m; sGate[8+t]=s;
      }
      GBAR();
    }
    if(t<8) sGate[8+t]=1.f/(sGate[8+t]+1e-8f);
    GBAR();

    // ---- gather pass ----
    for(int k0=beg; k0<end; k0+=64){
      int kc=min(64,end-k0);
      if(deg>64){
        for(int idx=t; idx<kc; idx+=256) sCEi[idx]=g_ce[k0+idx];
        GBAR();
        for(int idx=t; idx<kc*2; idx+=256){
          int j=idx>>1, q=idx&1;
          ((float4*)sAL)[j*2+q] = ((const float4*)(g_alpha+(size_t)sCEi[j]*8))[q];
        }
      }
      GBAR();
      for(int idx=t; idx<kc*8; idx+=256)
        sEW[idx]=__expf(sAL[idx]-sGate[idx&7])*sGate[8+(idx&7)];
      GBAR();
      for(int j=0;j<kc;j++){
        int e=sCEi[j];
        const float4* mp=(const float4*)(g_msg+(size_t)e*1600);
        const float* wj = sEW + j*8;
        for(int i=t;i<400;i+=256){
          float w=wj[(i&15)>>1];
          float4 v=mp[i];
          float4 a=sA4[i];
          FMA4(a,w,v);
          sA4[i]=a;
        }
      }
      GBAR();
    }

    // XN = x + agg @ proj_out
    {
      int r0=rg, r1=rg+16; bool v1=(r1<25);
      const float4* x4=(const float4*)(x+(size_t)n*1600);
      const float4* p4=(const float4*)sPO;
      float4 a0=x4[r0*16+c4];
      float4 a1=v1? x4[r1*16+c4] : Z4;
      #pragma unroll 8
      for(int k=0;k<64;k++){
        float4 wv=p4[k*16+c4];
        FMA4(a0,sA[r0*64+k],wv);
        if(v1) FMA4(a1,sA[r1*64+k],wv);
      }
      ((float4*)sXN)[r0*16+c4]=a0;
      if(v1) ((float4*)sXN)[r1*16+c4]=a1;
    }
    GBAR();
    if(t<64){
      float s=0.f;
      #pragma unroll
      for(int i=0;i<NC;i++){ float v=sXN[i*64+t]; s=fmaf(v,v,s); }
      sGate[t]=rsqrtf(s*(1.f/25.f)+1e-6f)*sGam[t];  // rinv temp
    }
    GBAR();
    {
      float4* sH4=(float4*)sH;
      const float4* xn4=(const float4*)sXN;
      const float4* rv4=(const float4*)sGate;
      for(int i=t;i<400;i+=256){ float4 v=xn4[i], r=rv4[i&15]; MUL4(v,r); sH4[i]=v; }
    }
    GBAR();
    float gacc=0.f;
    if(t<128){
      gacc=sGLB[t];
      #pragma unroll 8
      for(int c=0;c<64;c++) gacc=fmaf(sH[c],sGL[c*128+t],gacc);
    }
    GBAR();
    if(t<128) sGate[t]=gacc;
    // F1 = h @ ffn_w1 (+b1 row0)
    {
      int r0=rg8, r1=rg8+8, r2=rg8+16;
      const float4* w4=(const float4*)sW1f;
      float4 a0=Z4,a1=Z4,a2=Z4,a3=Z4;
      #pragma unroll 8
      for(int c=0;c<64;c++){
        float4 wv=w4[c*32+f4];
        FMA4(a0,sH[r0*64+c],wv);
        FMA4(a1,sH[r1*64+c],wv);
        FMA4(a2,sH[r2*64+c],wv);
        if(rg8==0) FMA4(a3,sH[24*64+c],wv);
      }
      if(rg8==0){ float4 b=((const float4*)sB1)[f4]; a0.x+=b.x;a0.y+=b.y;a0.z+=b.z;a0.w+=b.w; }
      float4* F4=(float4*)sF1;
      F4[r0*32+f4]=a0; F4[r1*32+f4]=a1; F4[r2*32+f4]=a2;
      if(rg8==0) F4[24*32+f4]=a3;
    }
    GBAR();
    // G2 = silu(to_grid @ F1)
    {
      int g0=rg8, g1=rg8+8, g2=rg8+16, g3=rg8+24, g4v=rg8+32; bool v4=(g4v<36);
      const float4* F4=(const float4*)sF1;
      float4* G4=(float4*)sG2;
      float4 a0=Z4,a1=Z4,a2=Z4,a3=Z4,a4=Z4;
      #pragma unroll
      for(int i=0;i<25;i++){
        float4 fv=F4[i*32+f4];
        FMA4(a0,sTG[g0*25+i],fv);
        FMA4(a1,sTG[g1*25+i],fv);
        FMA4(a2,sTG[g2*25+i],fv);
        FMA4(a3,sTG[g3*25+i],fv);
        if(v4) FMA4(a4,sTG[g4v*25+i],fv);
      }
      G4[g0*32+f4]=silu4(a0); G4[g1*32+f4]=silu4(a1);
      G4[g2*32+f4]=silu4(a2); G4[g3*32+f4]=silu4(a3);
      if(v4) G4[g4v*32+f4]=silu4(a4);
    }
    GBAR();
    // F1 := [silu(gate); from_grid @ G2]
    {
      int r0=rg8, r1=rg8+8, r2=rg8+16;
      const float4* G4=(const float4*)sG2;
      float4 a0=Z4,a1=Z4,a2=Z4,a3=Z4;
      #pragma unroll 6
      for(int g=0;g<36;g++){
        float4 gv=G4[g*32+f4];
        if(rg8>0) FMA4(a0,sFG[r0*36+g],gv);
        FMA4(a1,sFG[r1*36+g],gv);
        FMA4(a2,sFG[r2*36+g],gv);
        if(rg8==0) FMA4(a3,sFG[24*36+g],gv);
      }
      if(rg8==0) a0=silu4(((const float4*)sGate)[f4]);
      float4* F4=(float4*)sF1;
      F4[r0*32+f4]=a0; F4[r1*32+f4]=a1; F4[r2*32+f4]=a2;
      if(rg8==0) F4[24*32+f4]=a3;
    }
    GBAR();
    // out = XN + F1 @ ffn_w2 (+b2 row0)
    {
      int r0=rg, r1=rg+16; bool v1=(r1<25);
      const float4* w4=(const float4*)sW2;
      float4 a0=((const float4*)sXN)[r0*16+c4];
      float4 a1=v1? ((const float4*)sXN)[r1*16+c4] : Z4;
      if(r0==0){ float4 b=((const float4*)sB2)[c4]; a0.x+=b.x;a0.y+=b.y;a0.z+=b.z;a0.w+=b.w; }
      #pragma unroll 8
      for(int f=0;f<128;f++){
        float4 wv=w4[f*16+c4];
        FMA4(a0,sF1[r0*128+f],wv);
        if(v1) FMA4(a1,sF1[r1*128+f],wv);
      }
      float4* op=(float4*)(out+(size_t)n*1600);
      op[r0*16+c4]=a0;
      if(v1) op[r1*16+c4]=a1;
    }
    GBAR();
  }
}

extern "C" void kernel_launch(void* const* d_in, const int* in_sizes, int n_in,
                              void* d_out, int out_size) {
  const float* x    = (const float*)d_in[0];
  const int*   ei   = (const int*)d_in[1];
  const int*   zn   = (const int*)d_in[2];
  const float* ed   = (const float*)d_in[3];
  const float* wigr = (const float*)d_in[4];
  const float* stab = (const float*)d_in[5];
  const float* ttab = (const float*)d_in[6];
  const float* rw1  = (const float*)d_in[7];
  const float* rb1  = (const float*)d_in[8];
  const float* rw2  = (const float*)d_in[9];
  const float* rb2  = (const float*)d_in[10];
  const float* rw3  = (const float*)d_in[11];
  const float* rb3  = (const float*)d_in[12];
  const float* W1   = (const float*)d_in[13];
  const float* W0e  = (const float*)d_in[14];
  const float* adot = (const float*)d_in[15];
  const float* tg   = (const float*)d_in[16];
  const float* fg   = (const float*)d_in[17];
  const float* po   = (const float*)d_in[18];
  const float* gm1  = (const float*)d_in[19];
  const float* gm2  = (const float*)d_in[20];
  const float* glw  = (const float*)d_in[21];
  const float* glb  = (const float*)d_in[22];
  const float* fw1  = (const float*)d_in[23];
  const float* fb1  = (const float*)d_in[24];
  const float* fw2  = (const float*)d_in[25];
  const float* fb2  = (const float*)d_in[26];
  float* out = (float*)d_out;

  void *pcnt;
  cudaGetSymbolAddress(&pcnt, g_cnt);
  cudaMemsetAsync(pcnt, 0, NN*sizeof(int));

  const int RAD_SMEM  = 52864*4;
  const int EDGE_SMEM = (8192+24576+900+900+128 + 2*EPG)*4;   // 220640
  const int NODE_SMEM = (30856 + 2*NPG)*4;                    // 221216
  cudaFuncSetAttribute(k_rad,  cudaFuncAttributeMaxDynamicSharedMemorySize, RAD_SMEM);
  cudaFuncSetAttribute(k_edge, cudaFuncAttributeMaxDynamicSharedMemorySize, EDGE_SMEM);
  cudaFuncSetAttribute(k_node, cudaFuncAttributeMaxDynamicSharedMemorySize, NODE_SMEM);

  k_rms1<<<(NN+3)/4, dim3(64,4)>>>(x, gm1);
  k_count<<<(EE+255)/256, 256>>>(ei);
  k_scan<<<1, 1024>>>();
  k_fill<<<(EE+255)/256, 256>>>(ei);
  k_rad<<<296, 256, RAD_SMEM>>>(ed, ei, zn, stab, ttab, rw1, rb1, rw2, rb2, rw3, rb3);
  k_edge<<<148, 512, EDGE_SMEM>>>(wigr, ei, W1, W0e, adot, tg, fg);
  k_node<<<148, 512, NODE_SMEM>>>(x, out, po, gm2, glw, glb, fw1, fb1, fw2, fb2, tg, fg);
}